// round 11
// baseline (speedup 1.0000x reference)
#include <cuda_runtime.h>
#include <cuda_bf16.h>
#include <cuda_fp16.h>
#include <cstdint>
#include <cstddef>
#include <math.h>

// ---------------- problem constants ----------------
constexpr int EG  = 300000;   // edges
constexpr int TT  = 1000000;  // triplets
constexpr int NA  = 20000;    // atoms
constexpr int NM  = 1000;     // molecules
constexpr int E   = 128;      // embedding
constexpr int NR  = 6;
constexpr int NABF= 7;
constexpr int NB  = 3;

// ---------------- scratch layout (float granules) ----------------
constexpr size_t OFF_RBF  = 0;                                    // EG*6 f32
constexpr size_t OFF_CATH = OFF_RBF  + (size_t)EG*6;              // bf16[EG][384]
constexpr size_t OFF_CATL = OFF_CATH + (size_t)EG*192;
constexpr size_t OFF_XH   = OFF_CATL + (size_t)EG*192;            // bf16[EG][128]
constexpr size_t OFF_XL   = OFF_XH   + (size_t)EG*64;
constexpr size_t OFF_XKJ  = OFF_XL   + (size_t)EG*64;             // fp16[EG][128] (half the slot)
constexpr size_t OFF_AGGR = OFF_XKJ  + (size_t)EG*128;
constexpr size_t OFF_PA   = OFF_AGGR + (size_t)EG*128;            // 4 x f32[NA][128]
constexpr size_t OFF_HAT  = OFF_PA   + (size_t)4*NA*128;
constexpr size_t OFF_ROUT = OFF_HAT  + (size_t)NA*128;
constexpr size_t OFF_RSING= OFF_ROUT + (size_t)NA*128;
constexpr size_t OFF_STMP = OFF_RSING+ (size_t)NA*128;
constexpr size_t OFF_X0   = OFF_STMP + (size_t)NA*128;
constexpr size_t OFF_WT   = OFF_X0   + (size_t)NA*128;
// inside WT (bf16 element offsets relative to BF(base))
constexpr size_t WT_EMB_H = 0;
constexpr size_t WT_EMB_L = 49152;
constexpr size_t WT_O1_H  = 98304;
constexpr size_t WT_O1_L  = 163840;
constexpr size_t WT_OUT_H = 229376;
constexpr size_t WT_OUT_L = 294912;
constexpr size_t WT_ID1_H = 360448;
constexpr size_t WT_ID1_L = 425984;
constexpr size_t WT_ID2_H = 491520;
constexpr size_t WT_ID2_L = 557056;
constexpr size_t WT_JI_H  = 622592;
constexpr size_t WT_JI_L  = 671744;
constexpr size_t WT_KJ_H  = 720896;
constexpr size_t WT_KJ_L  = 770048;
constexpr size_t WT_RES_H = 819200;
constexpr size_t WT_RES_L = 868352;
constexpr size_t WT_TOTAL = 917504;
constexpr size_t TOTAL_F  = OFF_WT + WT_TOTAL;

__device__ float g_buf[TOTAL_F];

// ---------------- helpers ----------------
__device__ __forceinline__ uint32_t smem_u32(const void* p) {
    uint32_t a;
    asm("{ .reg .u64 t; cvta.to.shared.u64 t, %1; cvt.u32.u64 %0, t; }" : "=r"(a) : "l"(p));
    return a;
}
__device__ __forceinline__ float silu_f(float x) { return x / (1.f + __expf(-x)); }

#define LDSM4(rr, addr) \
    asm volatile("ldmatrix.sync.aligned.m8n8.x4.shared.b16 {%0,%1,%2,%3}, [%4];" \
        : "=r"((rr)[0]), "=r"((rr)[1]), "=r"((rr)[2]), "=r"((rr)[3]) : "r"(addr))

#define MMA_BF16(d, a, b0, b1) \
    asm volatile("mma.sync.aligned.m16n8k16.row.col.f32.bf16.bf16.f32 " \
        "{%0,%1,%2,%3},{%4,%5,%6,%7},{%8,%9},{%0,%1,%2,%3};" \
        : "+f"((d)[0]), "+f"((d)[1]), "+f"((d)[2]), "+f"((d)[3]) \
        : "r"((a)[0]), "r"((a)[1]), "r"((a)[2]), "r"((a)[3]), "r"(b0), "r"(b1))

#define CP_ASYNC16(dst, src) \
    asm volatile("cp.async.cg.shared.global [%0], [%1], 16;" :: "r"(dst), "l"(src) : "memory")
#define CP_COMMIT() asm volatile("cp.async.commit_group;" ::: "memory")
#define CP_WAIT0()  asm volatile("cp.async.wait_group 0;" ::: "memory")

#define RED4(ptr, a, b, c, dd) \
    asm volatile("red.global.add.v4.f32 [%0], {%1,%2,%3,%4};" \
        :: "l"(ptr), "f"(a), "f"(b), "f"(c), "f"(dd) : "memory")

__device__ __forceinline__ uint32_t pack_bf16_hi(float a, float b, float& la, float& lb) {
    __nv_bfloat162 h = __floats2bfloat162_rn(a, b);
    la = a - __bfloat162float(h.x);
    lb = b - __bfloat162float(h.y);
    return *(uint32_t*)&h;
}
__device__ __forceinline__ uint32_t pack_bf16(float a, float b) {
    __nv_bfloat162 h = __floats2bfloat162_rn(a, b);
    return *(uint32_t*)&h;
}

// ---------------- smem layout (bytes after 1024-align) ----------------
constexpr int TILE  = 16384;
constexpr int SM_AH   = 0;
constexpr int SM_AL   = SM_AH + TILE;
constexpr int SM_BH   = SM_AL + TILE;
constexpr int SM_BL   = SM_BH + TILE;
constexpr int SM_WMUL = 65536;
constexpr int SM_WSC  = 68608;
constexpr int SM_RBF6 = 71680;
constexpr int SM_BIAS = 74752;
constexpr int SM_END  = 75264;
constexpr int SMEM_DYN = SM_END + 1024 + 128;

// ---------------- launch: rbf + zero PA buffers ----------------
__global__ void rbf_kernel(const float* __restrict__ R,
                           const int* __restrict__ idx_i,
                           const int* __restrict__ idx_j,
                           float* __restrict__ rbf,
                           float* __restrict__ pa4)
{
    const float PI_F = 3.14159265358979323846f;
    const float c = sqrtf(2.f / 5.f);
    int gtid = blockIdx.x * blockDim.x + threadIdx.x;
    int gstr = gridDim.x * blockDim.x;
    size_t pn = (size_t)4*NA*128/4;
    float4 z = make_float4(0.f,0.f,0.f,0.f);
    for (size_t i = gtid; i < pn; i += gstr) ((float4*)pa4)[i] = z;
    for (int e = gtid; e < EG; e += gstr) {
        int i = idx_i[e], j = idx_j[e];
        float dx = R[3*i+0] - R[3*j+0];
        float dy = R[3*i+1] - R[3*j+1];
        float dz = R[3*i+2] - R[3*j+2];
        float d = sqrtf(dx*dx + dy*dy + dz*dz);
        d = fmaxf(d, 1e-2f);
        float inv = 1.f / d;
        float arg = d * (PI_F / 5.f);
        float s1, c1;
        __sincosf(arg, &s1, &c1);
        float tc = 2.f * c1;
        float sm1 = 0.f, s = s1;
        #pragma unroll
        for (int r = 0; r < NR; r++) {
            rbf[(size_t)e*NR + r] = c * s * inv;
            float nx = tc * s - sm1;
            sm1 = s; s = nx;
        }
    }
}

__global__ void x0_kernel(const int* __restrict__ Z,
                          const float* __restrict__ emb,
                          float* __restrict__ x0)
{
    size_t total = (size_t)NA * E;
    for (size_t idx = blockIdx.x * (size_t)blockDim.x + threadIdx.x; idx < total;
         idx += (size_t)gridDim.x * blockDim.x) {
        int a = (int)(idx >> 7);
        int c = (int)(idx & 127);
        x0[idx] = emb[(size_t)Z[a]*E + c];
    }
}

// coalesced buildcat: 128 threads = 2 edges x 64 column-pairs; u32 bf16x2 stores
__global__ __launch_bounds__(128) void buildcat_kernel(
    const int* __restrict__ Z,
    const int* __restrict__ idx_i,
    const int* __restrict__ idx_j,
    const float* __restrict__ emb,
    const float* __restrict__ Wrbf,
    const float* __restrict__ rbf,
    __nv_bfloat16* __restrict__ ch_,
    __nv_bfloat16* __restrict__ cl_)
{
    __shared__ float ws[NR*E];
    for (int k = threadIdx.x; k < NR*E; k += 128) ws[k] = Wrbf[k];
    __syncthreads();
    int half = threadIdx.x >> 6;
    int c2 = threadIdx.x & 63;
    int c0 = c2 * 2;
    for (int eb = blockIdx.x * 2; eb < EG; eb += gridDim.x * 2) {
        int e = eb + half;
        if (e >= EG) continue;
        int ai = idx_i[e], aj = idx_j[e];
        float r0 = rbf[(size_t)e*NR+0], r1 = rbf[(size_t)e*NR+1], r2 = rbf[(size_t)e*NR+2];
        float r3 = rbf[(size_t)e*NR+3], r4 = rbf[(size_t)e*NR+4], r5 = rbf[(size_t)e*NR+5];
        float s0 = r0*ws[c0]     + r1*ws[E+c0]     + r2*ws[2*E+c0]
                 + r3*ws[3*E+c0] + r4*ws[4*E+c0]   + r5*ws[5*E+c0];
        float s1 = r0*ws[c0+1]   + r1*ws[E+c0+1]   + r2*ws[2*E+c0+1]
                 + r3*ws[3*E+c0+1] + r4*ws[4*E+c0+1] + r5*ws[5*E+c0+1];
        s0 = silu_f(s0); s1 = silu_f(s1);
        float2 vi = *(const float2*)&emb[(size_t)Z[ai]*E + c0];
        float2 vj = *(const float2*)&emb[(size_t)Z[aj]*E + c0];
        size_t base = (size_t)e * 384;
        float l0, l1;
        uint32_t h;
        h = pack_bf16_hi(vi.x, vi.y, l0, l1);
        *(uint32_t*)&ch_[base + c0] = h;
        *(uint32_t*)&cl_[base + c0] = pack_bf16(l0, l1);
        h = pack_bf16_hi(vj.x, vj.y, l0, l1);
        *(uint32_t*)&ch_[base + 128 + c0] = h;
        *(uint32_t*)&cl_[base + 128 + c0] = pack_bf16(l0, l1);
        h = pack_bf16_hi(s0, s1, l0, l1);
        *(uint32_t*)&ch_[base + 256 + c0] = h;
        *(uint32_t*)&cl_[base + 256 + c0] = pack_bf16(l0, l1);
    }
}

// ---- batched transpose+split ----
struct TsplitJobs {
    const float* src[8];
    float* dst_h[8];
    float* dst_l[8];
    int K[8];
    int tot[8];
};
__global__ void tsplit_all_kernel(TsplitJobs jobs)
{
    int j = blockIdx.y;
    const float* s = jobs.src[j];
    __nv_bfloat16* h = (__nv_bfloat16*)jobs.dst_h[j];
    __nv_bfloat16* l = (__nv_bfloat16*)jobs.dst_l[j];
    int K = jobs.K[j];
    int tot = jobs.tot[j];
    int per = K * 128;
    for (int idx = blockIdx.x * blockDim.x + threadIdx.x; idx < tot;
         idx += gridDim.x * blockDim.x) {
        int b = idx / per;
        int rem = idx - b * per;
        int k = rem >> 7, n = rem & 127;
        float v = s[idx];
        __nv_bfloat16 hi = __float2bfloat16(v);
        float lo = v - __bfloat162float(hi);
        h[(size_t)b*per + (size_t)n*K + k] = hi;
        l[(size_t)b*per + (size_t)n*K + k] = __float2bfloat16(lo);
    }
}

// ---------------- mma.sync bf16x3 GEMM ----------------
__global__ __launch_bounds__(256) void gemm_mma(
    const float* __restrict__ A,
    const __nv_bfloat16* __restrict__ A16h,
    const __nv_bfloat16* __restrict__ A16l,
    const __nv_bfloat16* __restrict__ Bh,
    const __nv_bfloat16* __restrict__ Bl,
    const float* __restrict__ bias,
    const float* __restrict__ mulW,
    const float* __restrict__ addp,
    const float* __restrict__ scW,
    const int* __restrict__ sc_idx, float* __restrict__ sc_out,
    const float* __restrict__ rbf,
    float* __restrict__ C,
    __nv_bfloat16* __restrict__ C16h,
    __nv_bfloat16* __restrict__ C16l,
    __half* __restrict__ Cf16,
    int M, int K, int act)
{
    extern __shared__ char smraw[];
    char* sm = (char*)(((uintptr_t)smraw + 1023) & ~(uintptr_t)1023);
    uint32_t smb = smem_u32(sm);
    float* wmul_s = (float*)(sm + SM_WMUL);
    float* wsc_s  = (float*)(sm + SM_WSC);
    float* rbf6   = (float*)(sm + SM_RBF6);
    float* bias_s = (float*)(sm + SM_BIAS);

    int tid = threadIdx.x;
    int lane = tid & 31;
    int wid = tid >> 5;
    int bm = blockIdx.x * 128;
    int need_rbf = (mulW != nullptr) || (scW != nullptr);

    for (int k = tid; k < NR*E; k += 256) {
        if (mulW) wmul_s[k] = mulW[k];
        if (scW)  wsc_s[k]  = scW[k];
    }
    for (int k = tid; k < E; k += 256) bias_s[k] = bias ? bias[k] : 0.f;
    if (need_rbf && tid < 128) {
        int g = bm + tid; if (g >= M) g = M - 1;
        #pragma unroll
        for (int q = 0; q < NR; q++) rbf6[tid*NR + q] = rbf[(size_t)g*NR + q];
    }
    __syncthreads();

    int wm = (wid & 3) * 32;
    int wn = (wid >> 2) * 64;
    int lq = lane >> 2;
    int lr4 = lane & 3;
    int r  = lane & 7;
    int mi = lane >> 3;
    uint32_t AHb = smb + SM_AH + (uint32_t)((wm + (mi&1)*8 + r) * 128);
    uint32_t ALb = AHb + TILE;
    int a_chsel = mi >> 1;
    uint32_t BHb = smb + SM_BH + (uint32_t)((wn + ((mi>>1)&1)*8 + r) * 128);
    uint32_t BLb = BHb + TILE;
    int b_chsel = mi & 1;

    float acc[2][8][4];
    #pragma unroll
    for (int a0 = 0; a0 < 2; a0++)
        #pragma unroll
        for (int b0 = 0; b0 < 8; b0++)
            #pragma unroll
            for (int c0 = 0; c0 < 4; c0++) acc[a0][b0][c0] = 0.f;

    int nch = K >> 6;
    for (int c = 0; c < nch; c++) {
        int kc = c << 6;

        #pragma unroll
        for (int u = 0; u < 8; u++) {
            int f = u*256 + tid;
            int which = f >> 10;
            int g2 = f & 1023;
            int n = g2 >> 3, ch = g2 & 7;
            const __nv_bfloat16* src = (which ? Bl : Bh) + (size_t)n*K + kc + ch*8;
            uint32_t dst = smb + (which ? SM_BL : SM_BH)
                         + (uint32_t)(n*128 + ((ch ^ (n & 7)) << 4));
            CP_ASYNC16(dst, src);
        }
        if (A16h) {
            #pragma unroll
            for (int u = 0; u < 8; u++) {
                int f = u*256 + tid;
                int which = f >> 10;
                int g2 = f & 1023;
                int rr = g2 >> 3, ch = g2 & 7;
                int g = bm + rr; if (g >= M) g = M - 1;
                const __nv_bfloat16* src = (which ? A16l : A16h) + (size_t)g*K + kc + ch*8;
                uint32_t dst = smb + (which ? SM_AL : SM_AH)
                             + (uint32_t)(rr*128 + ((ch ^ (rr & 7)) << 4));
                CP_ASYNC16(dst, src);
            }
            CP_COMMIT();
            CP_WAIT0();
        } else {
            CP_COMMIT();
            #pragma unroll
            for (int u = 0; u < 4; u++) {
                int f = u*256 + tid;
                int rr = f >> 3, ch = f & 7;
                int g = bm + rr;
                int k = kc + ch*8;
                float v[8];
                if (g < M) {
                    float4 p0 = *(const float4*)&A[(size_t)g*K + k];
                    float4 p1 = *(const float4*)&A[(size_t)g*K + k + 4];
                    v[0]=p0.x; v[1]=p0.y; v[2]=p0.z; v[3]=p0.w;
                    v[4]=p1.x; v[5]=p1.y; v[6]=p1.z; v[7]=p1.w;
                } else {
                    #pragma unroll
                    for (int e2 = 0; e2 < 8; e2++) v[e2] = 0.f;
                }
                uint4 hb, lb;
                float l0, l1;
                hb.x = pack_bf16_hi(v[0], v[1], l0, l1); lb.x = pack_bf16(l0, l1);
                hb.y = pack_bf16_hi(v[2], v[3], l0, l1); lb.y = pack_bf16(l0, l1);
                hb.z = pack_bf16_hi(v[4], v[5], l0, l1); lb.z = pack_bf16(l0, l1);
                hb.w = pack_bf16_hi(v[6], v[7], l0, l1); lb.w = pack_bf16(l0, l1);
                uint32_t sw = (uint32_t)(rr*128 + ((ch ^ (rr & 7)) << 4));
                *(uint4*)(sm + SM_AH + sw) = hb;
                *(uint4*)(sm + SM_AL + sw) = lb;
            }
            CP_WAIT0();
        }
        __syncthreads();

        #pragma unroll
        for (int ks = 0; ks < 4; ks++) {
            uint32_t aswz = (uint32_t)(((2*ks + a_chsel) ^ r) << 4);
            uint32_t bswz = (uint32_t)(((2*ks + b_chsel) ^ r) << 4);
            uint32_t ah[2][4], al[2][4];
            LDSM4(ah[0], AHb + aswz);
            LDSM4(ah[1], AHb + 2048 + aswz);
            LDSM4(al[0], ALb + aswz);
            LDSM4(al[1], ALb + 2048 + aswz);
            #pragma unroll
            for (int p = 0; p < 4; p++) {
                uint32_t bh[4], bl[4];
                LDSM4(bh, BHb + (uint32_t)(p*2048) + bswz);
                LDSM4(bl, BLb + (uint32_t)(p*2048) + bswz);
                #pragma unroll
                for (int mt = 0; mt < 2; mt++) {
                    MMA_BF16(acc[mt][2*p+0], ah[mt], bh[0], bh[1]);
                    MMA_BF16(acc[mt][2*p+0], ah[mt], bl[0], bl[1]);
                    MMA_BF16(acc[mt][2*p+0], al[mt], bh[0], bh[1]);
                    MMA_BF16(acc[mt][2*p+1], ah[mt], bh[2], bh[3]);
                    MMA_BF16(acc[mt][2*p+1], ah[mt], bl[2], bl[3]);
                    MMA_BF16(acc[mt][2*p+1], al[mt], bh[2], bh[3]);
                }
            }
        }
        __syncthreads();
    }

    // ---- epilogue (no early exits: keeps warps converged for shfl pairing) ----
    #pragma unroll
    for (int mt = 0; mt < 2; mt++) {
        int lrbase = wm + mt*16 + lq;
        #pragma unroll
        for (int h = 0; h < 2; h++) {
            int lrow = lrbase + h*8;
            int row = bm + lrow;
            bool valid = (row < M);
            int asc = (scW && valid) ? sc_idx[row] : 0;
            #pragma unroll
            for (int nt = 0; nt < 8; nt++) {
                int col = wn + nt*8 + lr4*2;
                float v0 = acc[mt][nt][2*h+0] + bias_s[col];
                float v1 = acc[mt][nt][2*h+1] + bias_s[col+1];
                if (act) { v0 = silu_f(v0); v1 = silu_f(v1); }
                if (mulW) {
                    float d0 = 0.f, d1 = 0.f;
                    #pragma unroll
                    for (int q = 0; q < NR; q++) {
                        float rq = rbf6[lrow*NR + q];
                        d0 += rq * wmul_s[q*E + col];
                        d1 += rq * wmul_s[q*E + col + 1];
                    }
                    v0 *= d0; v1 *= d1;
                }
                if (addp && valid) {
                    float2 av = *(const float2*)&addp[(size_t)row*128 + col];
                    v0 += av.x; v1 += av.y;
                }
                if (C && valid) *(float2*)&C[(size_t)row*128 + col] = make_float2(v0, v1);
                if (C16h && valid) {
                    float l0, l1;
                    uint32_t hb = pack_bf16_hi(v0, v1, l0, l1);
                    uint32_t lb = pack_bf16(l0, l1);
                    *(uint32_t*)&C16h[(size_t)row*128 + col] = hb;
                    *(uint32_t*)&C16l[(size_t)row*128 + col] = lb;
                }
                if (Cf16 && valid) {
                    __half2 hv = __floats2half2_rn(v0, v1);
                    *(__half2*)&Cf16[(size_t)row*128 + col] = hv;
                }
                if (scW) {
                    float g0 = 0.f, g1 = 0.f;
                    #pragma unroll
                    for (int q = 0; q < NR; q++) {
                        float rq = rbf6[lrow*NR + q];
                        g0 += rq * wsc_s[q*E + col];
                        g1 += rq * wsc_s[q*E + col + 1];
                    }
                    float p0 = g0*v0, p1 = g1*v1;
                    // lanes x and x^1 hold adjacent col pairs of the SAME row:
                    // merge into one red.v4 issued by even lanes (half the atomic ops)
                    float q0 = __shfl_xor_sync(0xffffffffu, p0, 1);
                    float q1 = __shfl_xor_sync(0xffffffffu, p1, 1);
                    if (valid && !(lane & 1))
                        RED4(&sc_out[(size_t)asc*128 + col], p0, p1, q0, q1);
                }
            }
        }
    }
}

// ---------------- triplet messages + atomic scatter (fp16 xkj gather) ----------------
__global__ __launch_bounds__(256) void triplet_kernel(
    const __half* __restrict__ xkj,
    const float* __restrict__ cosik,
    const int* __restrict__ idx_kj,
    const int* __restrict__ idx_ji,
    const float* __restrict__ Wabf,       // [7,128]
    float* __restrict__ aggr)
{
    __shared__ float ws[NABF*E];
    for (int k = threadIdx.x; k < NABF*E; k += 256) ws[k] = Wabf[k];
    __syncthreads();
    int lane = threadIdx.x & 31;
    int warp = (blockIdx.x * 256 + threadIdx.x) >> 5;
    int nwarps = (gridDim.x * 256) >> 5;
    int c = lane << 2;
    for (int t = warp; t < TT; t += nwarps) {
        int ekj = idx_kj[t];
        int eji = idx_ji[t];
        float x = fminf(1.f, fmaxf(-1.f, cosik[t]));
        float a0 = 1.f, a1 = x;
        float a2 = 2.f*x*a1 - a0;
        float a3 = 2.f*x*a2 - a1;
        float a4 = 2.f*x*a3 - a2;
        float a5 = 2.f*x*a4 - a3;
        float a6 = 2.f*x*a5 - a4;
        uint2 raw = *(const uint2*)&xkj[(size_t)ekj*128 + c];   // 4 halves = 8 B/lane
        float2 x01 = __half22float2(*(__half2*)&raw.x);
        float2 x23 = __half22float2(*(__half2*)&raw.y);
        float xv[4] = {x01.x, x01.y, x23.x, x23.y};
        float m[4];
        #pragma unroll
        for (int j = 0; j < 4; j++) {
            int cc = c + j;
            m[j] = a0*ws[cc] + a1*ws[E+cc] + a2*ws[2*E+cc] + a3*ws[3*E+cc]
                 + a4*ws[4*E+cc] + a5*ws[5*E+cc] + a6*ws[6*E+cc];
        }
        RED4(&aggr[(size_t)eji*128 + c], xv[0]*m[0], xv[1]*m[1], xv[2]*m[2], xv[3]*m[3]);
    }
}

// ---------------- final molecule reduction ----------------
__global__ void final_kernel(const float* __restrict__ ro,
                             const float* __restrict__ rs,
                             const int* __restrict__ bseg,
                             const float* __restrict__ cmp_p,
                             const float* __restrict__ csg_p,
                             float* __restrict__ out)
{
    float cmp = cmp_p[0], csg = csg_p[0];
    size_t total = (size_t)NA * 32;
    for (size_t idx = blockIdx.x * (size_t)blockDim.x + threadIdx.x; idx < total;
         idx += (size_t)gridDim.x * blockDim.x) {
        int a = (int)(idx >> 5);
        int c = (int)(idx & 31) << 2;
        int m = bseg[a];
        float4 o = *(const float4*)&ro[(size_t)a*128 + c];
        float4 s = *(const float4*)&rs[(size_t)a*128 + c];
        RED4(&out[(size_t)m*128 + c],
             cmp*o.x + csg*s.x, cmp*o.y + csg*s.y,
             cmp*o.z + csg*s.z, cmp*o.w + csg*s.w);
    }
}

// ---------------- host orchestration (serial stream 0) ----------------
extern "C" void kernel_launch(void* const* d_in, const int* in_sizes, int n_in,
                              void* d_out, int out_size)
{
    const int*   Z      = (const int*)  d_in[0];
    const float* R      = (const float*)d_in[1];
    const int*   bseg   = (const int*)  d_in[2];
    const int*   idx_i  = (const int*)  d_in[3];
    const int*   idx_j  = (const int*)  d_in[4];
    const int*   idx_kj = (const int*)  d_in[5];
    const int*   idx_ji = (const int*)  d_in[6];
    const float* cosik  = (const float*)d_in[7];
    const float* emb    = (const float*)d_in[8];
    const float* Wrbf   = (const float*)d_in[9];
    const float* Wemb   = (const float*)d_in[10];
    const float* bemb   = (const float*)d_in[11];
    const float* Worbf  = (const float*)d_in[12];
    const float* Wo1    = (const float*)d_in[13];
    const float* bo1    = (const float*)d_in[14];
    const float* Wout   = (const float*)d_in[15];
    const float* Wid1   = (const float*)d_in[16];
    const float* bid1   = (const float*)d_in[17];
    const float* Wid2   = (const float*)d_in[18];
    const float* Wji    = (const float*)d_in[19];
    const float* bji    = (const float*)d_in[20];
    const float* Wkj    = (const float*)d_in[21];
    const float* bkj    = (const float*)d_in[22];
    const float* Wirbf  = (const float*)d_in[23];
    const float* Wabf   = (const float*)d_in[24];
    const float* Wres   = (const float*)d_in[25];
    const float* bres   = (const float*)d_in[26];
    const float* cmp    = (const float*)d_in[27];
    const float* csg    = (const float*)d_in[28];
    float* out = (float*)d_out;

    cudaFuncSetAttribute(gemm_mma, cudaFuncAttributeMaxDynamicSharedMemorySize, SMEM_DYN);

    float* buf = nullptr;
    cudaGetSymbolAddress((void**)&buf, g_buf);
    float* RBF   = buf + OFF_RBF;
    __nv_bfloat16* CATH = (__nv_bfloat16*)(buf + OFF_CATH);
    __nv_bfloat16* CATL = (__nv_bfloat16*)(buf + OFF_CATL);
    __nv_bfloat16* XH   = (__nv_bfloat16*)(buf + OFF_XH);
    __nv_bfloat16* XL   = (__nv_bfloat16*)(buf + OFF_XL);
    __half* XKJ16 = (__half*)(buf + OFF_XKJ);
    float* AGGR  = buf + OFF_AGGR;
    float* PA    = buf + OFF_PA;
    float* HAT   = buf + OFF_HAT;
    float* ROUT  = buf + OFF_ROUT;
    float* RSING = buf + OFF_RSING;
    float* STMP  = buf + OFF_STMP;
    float* X0    = buf + OFF_X0;
    float* WT    = buf + OFF_WT;

    #define BF(off) ((__nv_bfloat16*)(WT + (off)))
    #define PAB(b)  (PA + (size_t)(b)*NA*128)

    const int GE = (EG + 127) / 128;
    const int GA = (NA + 127) / 128;

    rbf_kernel<<<1024, 256>>>(R, idx_i, idx_j, RBF, PA);
    x0_kernel<<<1024, 256>>>(Z, emb, X0);
    buildcat_kernel<<<4096, 128>>>(Z, idx_i, idx_j, emb, Wrbf, RBF, CATH, CATL);
    {
        TsplitJobs j;
        j.src[0]=Wemb; j.dst_h[0]=(float*)BF(WT_EMB_H); j.dst_l[0]=(float*)BF(WT_EMB_L); j.K[0]=384; j.tot[0]=384*128;
        j.src[1]=Wo1;  j.dst_h[1]=(float*)BF(WT_O1_H);  j.dst_l[1]=(float*)BF(WT_O1_L);  j.K[1]=128; j.tot[1]=4*128*128;
        j.src[2]=Wout; j.dst_h[2]=(float*)BF(WT_OUT_H); j.dst_l[2]=(float*)BF(WT_OUT_L); j.K[2]=128; j.tot[2]=4*128*128;
        j.src[3]=Wid1; j.dst_h[3]=(float*)BF(WT_ID1_H); j.dst_l[3]=(float*)BF(WT_ID1_L); j.K[3]=128; j.tot[3]=4*128*128;
        j.src[4]=Wid2; j.dst_h[4]=(float*)BF(WT_ID2_H); j.dst_l[4]=(float*)BF(WT_ID2_L); j.K[4]=128; j.tot[4]=4*128*128;
        j.src[5]=Wji;  j.dst_h[5]=(float*)BF(WT_JI_H);  j.dst_l[5]=(float*)BF(WT_JI_L);  j.K[5]=128; j.tot[5]=3*128*128;
        j.src[6]=Wkj;  j.dst_h[6]=(float*)BF(WT_KJ_H);  j.dst_l[6]=(float*)BF(WT_KJ_L);  j.K[6]=128; j.tot[6]=3*128*128;
        j.src[7]=Wres; j.dst_h[7]=(float*)BF(WT_RES_H); j.dst_l[7]=(float*)BF(WT_RES_L); j.K[7]=128; j.tot[7]=3*128*128;
        tsplit_all_kernel<<<dim3(64, 8), 256>>>(j);
    }

    // embedding GEMM (+fused output-block-0 scatter into PA0)
    gemm_mma<<<GE, 256, SMEM_DYN>>>(nullptr, CATH, CATL,
                                    BF(WT_EMB_H), BF(WT_EMB_L), bemb,
                                    nullptr, nullptr,
                                    Worbf, idx_i, PAB(0), RBF,
                                    nullptr, XH, XL, nullptr, EG, 384, 1);

    for (int i = 0; i < NB; i++) {
        size_t wo = (size_t)i * 128 * 128;
        // x_kj (fp16 out) = silu(x@Wkj+b) * (rbf@Wirbf)
        gemm_mma<<<GE, 256, SMEM_DYN>>>(nullptr, XH, XL,
                                        BF(WT_KJ_H) + wo, BF(WT_KJ_L) + wo, bkj + (size_t)i*E,
                                        Wirbf + (size_t)i*NR*E, nullptr,
                                        nullptr, nullptr, nullptr, RBF,
                                        nullptr, nullptr, nullptr, XKJ16, EG, 128, 1);
        // x_ji -> AGGR
        gemm_mma<<<GE, 256, SMEM_DYN>>>(nullptr, XH, XL,
                                        BF(WT_JI_H) + wo, BF(WT_JI_L) + wo, bji + (size_t)i*E,
                                        nullptr, nullptr, nullptr, nullptr, nullptr, nullptr,
                                        AGGR, nullptr, nullptr, nullptr, EG, 128, 1);
        // triplet atomic accumulate into AGGR (fp16 gather)
        triplet_kernel<<<2048, 256>>>(XKJ16, cosik, idx_kj, idx_ji,
                                      Wabf + (size_t)i*NABF*E, AGGR);
        // x = h + silu(h@Wres+b) -> XH/XL; fused output-block(i+1) scatter -> PA(i+1)
        gemm_mma<<<GE, 256, SMEM_DYN>>>(AGGR, nullptr, nullptr,
                                        BF(WT_RES_H) + wo, BF(WT_RES_L) + wo, bres + (size_t)i*E,
                                        nullptr, AGGR,
                                        Worbf + (size_t)(i+1)*NR*E, idx_i, PAB(i+1), RBF,
                                        nullptr, XH, XL, nullptr, EG, 128, 1);
    }

    // output chains (blocks 0..3)
    for (int b = 0; b <= NB; b++) {
        size_t wo1 = (size_t)b * 128 * 128;
        gemm_mma<<<GA, 256, SMEM_DYN>>>(PAB(b), nullptr, nullptr,
                                        BF(WT_O1_H) + wo1, BF(WT_O1_L) + wo1, bo1 + (size_t)b*E,
                                        nullptr, nullptr, nullptr, nullptr, nullptr, nullptr,
                                        HAT, nullptr, nullptr, nullptr, NA, 128, 1);
        gemm_mma<<<GA, 256, SMEM_DYN>>>(HAT, nullptr, nullptr,
                                        BF(WT_OUT_H) + wo1, BF(WT_OUT_L) + wo1, nullptr,
                                        nullptr, (b == 0) ? nullptr : ROUT,
                                        nullptr, nullptr, nullptr, nullptr,
                                        ROUT, nullptr, nullptr, nullptr, NA, 128, 0);
    }

    // identity chain
    gemm_mma<<<GA, 256, SMEM_DYN>>>(X0, nullptr, nullptr, BF(WT_ID1_H), BF(WT_ID1_L), bid1,
                                    nullptr, nullptr, nullptr, nullptr, nullptr, nullptr,
                                    STMP, nullptr, nullptr, nullptr, NA, 128, 1);
    gemm_mma<<<GA, 256, SMEM_DYN>>>(STMP, nullptr, nullptr, BF(WT_ID2_H), BF(WT_ID2_L), nullptr,
                                    nullptr, nullptr, nullptr, nullptr, nullptr, nullptr,
                                    RSING, nullptr, nullptr, nullptr, NA, 128, 0);
    for (int b = 1; b <= NB; b++) {
        size_t wo1 = (size_t)b * 128 * 128;
        gemm_mma<<<GA, 256, SMEM_DYN>>>(RSING, nullptr, nullptr,
                                        BF(WT_ID1_H) + wo1, BF(WT_ID1_L) + wo1, bid1 + (size_t)b*E,
                                        nullptr, nullptr, nullptr, nullptr, nullptr, nullptr,
                                        STMP, nullptr, nullptr, nullptr, NA, 128, 1);
        gemm_mma<<<GA, 256, SMEM_DYN>>>(STMP, nullptr, nullptr,
                                        BF(WT_ID2_H) + wo1, BF(WT_ID2_L) + wo1, nullptr,
                                        nullptr, RSING, nullptr, nullptr, nullptr, nullptr,
                                        RSING, nullptr, nullptr, nullptr, NA, 128, 0);
    }

    // final
    cudaMemsetAsync(out, 0, (size_t)NM*E*sizeof(float));
    final_kernel<<<512, 256>>>(ROUT, RSING, bseg, cmp, csg, out);
}

// round 12
// speedup vs baseline: 1.0556x; 1.0556x over previous
#include <cuda_runtime.h>
#include <cuda_bf16.h>
#include <cstdint>
#include <cstddef>
#include <math.h>

// ---------------- problem constants ----------------
constexpr int EG  = 300000;   // edges
constexpr int TT  = 1000000;  // triplets
constexpr int NA  = 20000;    // atoms
constexpr int NM  = 1000;     // molecules
constexpr int E   = 128;      // embedding
constexpr int NR  = 6;
constexpr int NABF= 7;
constexpr int NB  = 3;

// ---------------- scratch layout (float granules) ----------------
constexpr size_t OFF_RBF  = 0;                                    // EG*6 f32
constexpr size_t OFF_CATH = OFF_RBF  + (size_t)EG*6;              // bf16[EG][384]
constexpr size_t OFF_CATL = OFF_CATH + (size_t)EG*192;
constexpr size_t OFF_XH   = OFF_CATL + (size_t)EG*192;            // bf16[EG][128]
constexpr size_t OFF_XL   = OFF_XH   + (size_t)EG*64;
constexpr size_t OFF_XKJ  = OFF_XL   + (size_t)EG*64;             // f32[EG][128]
constexpr size_t OFF_AGGR = OFF_XKJ  + (size_t)EG*128;
constexpr size_t OFF_PA   = OFF_AGGR + (size_t)EG*128;            // 4 x f32[NA][128]
constexpr size_t OFF_HAT  = OFF_PA   + (size_t)4*NA*128;
constexpr size_t OFF_ROUT = OFF_HAT  + (size_t)NA*128;
constexpr size_t OFF_RSING= OFF_ROUT + (size_t)NA*128;
constexpr size_t OFF_STMP = OFF_RSING+ (size_t)NA*128;
constexpr size_t OFF_X0   = OFF_STMP + (size_t)NA*128;
constexpr size_t OFF_WT   = OFF_X0   + (size_t)NA*128;
// inside WT (bf16 element offsets relative to BF(base))
constexpr size_t WT_EMB_H = 0;
constexpr size_t WT_EMB_L = 49152;
constexpr size_t WT_O1_H  = 98304;
constexpr size_t WT_O1_L  = 163840;
constexpr size_t WT_OUT_H = 229376;
constexpr size_t WT_OUT_L = 294912;
constexpr size_t WT_ID1_H = 360448;
constexpr size_t WT_ID1_L = 425984;
constexpr size_t WT_ID2_H = 491520;
constexpr size_t WT_ID2_L = 557056;
constexpr size_t WT_JI_H  = 622592;
constexpr size_t WT_JI_L  = 671744;
constexpr size_t WT_KJ_H  = 720896;
constexpr size_t WT_KJ_L  = 770048;
constexpr size_t WT_RES_H = 819200;
constexpr size_t WT_RES_L = 868352;
constexpr size_t WT_TOTAL = 917504;
constexpr size_t TOTAL_F  = OFF_WT + WT_TOTAL;

__device__ float g_buf[TOTAL_F];

// ---------------- helpers ----------------
__device__ __forceinline__ uint32_t smem_u32(const void* p) {
    uint32_t a;
    asm("{ .reg .u64 t; cvta.to.shared.u64 t, %1; cvt.u32.u64 %0, t; }" : "=r"(a) : "l"(p));
    return a;
}
__device__ __forceinline__ float silu_f(float x) { return x / (1.f + __expf(-x)); }

#define LDSM4(rr, addr) \
    asm volatile("ldmatrix.sync.aligned.m8n8.x4.shared.b16 {%0,%1,%2,%3}, [%4];" \
        : "=r"((rr)[0]), "=r"((rr)[1]), "=r"((rr)[2]), "=r"((rr)[3]) : "r"(addr))

#define MMA_BF16(d, a, b0, b1) \
    asm volatile("mma.sync.aligned.m16n8k16.row.col.f32.bf16.bf16.f32 " \
        "{%0,%1,%2,%3},{%4,%5,%6,%7},{%8,%9},{%0,%1,%2,%3};" \
        : "+f"((d)[0]), "+f"((d)[1]), "+f"((d)[2]), "+f"((d)[3]) \
        : "r"((a)[0]), "r"((a)[1]), "r"((a)[2]), "r"((a)[3]), "r"(b0), "r"(b1))

#define CP_ASYNC16(dst, src) \
    asm volatile("cp.async.cg.shared.global [%0], [%1], 16;" :: "r"(dst), "l"(src) : "memory")
#define CP_COMMIT() asm volatile("cp.async.commit_group;" ::: "memory")
#define CP_WAIT0()  asm volatile("cp.async.wait_group 0;" ::: "memory")

#define RED4(ptr, a, b, c, dd) \
    asm volatile("red.global.add.v4.f32 [%0], {%1,%2,%3,%4};" \
        :: "l"(ptr), "f"(a), "f"(b), "f"(c), "f"(dd) : "memory")
#define RED2(ptr, a, b) \
    asm volatile("red.global.add.v2.f32 [%0], {%1,%2};" \
        :: "l"(ptr), "f"(a), "f"(b) : "memory")

__device__ __forceinline__ uint32_t pack_bf16_hi(float a, float b, float& la, float& lb) {
    __nv_bfloat162 h = __floats2bfloat162_rn(a, b);
    la = a - __bfloat162float(h.x);
    lb = b - __bfloat162float(h.y);
    return *(uint32_t*)&h;
}
__device__ __forceinline__ uint32_t pack_bf16(float a, float b) {
    __nv_bfloat162 h = __floats2bfloat162_rn(a, b);
    return *(uint32_t*)&h;
}

// ---------------- smem layout (bytes after 1024-align) ----------------
constexpr int TILE  = 16384;
constexpr int SM_AH   = 0;
constexpr int SM_AL   = SM_AH + TILE;
constexpr int SM_BH   = SM_AL + TILE;
constexpr int SM_BL   = SM_BH + TILE;
constexpr int SM_WMUL = 65536;
constexpr int SM_WSC  = 68608;
constexpr int SM_RBF6 = 71680;
constexpr int SM_BIAS = 74752;
constexpr int SM_END  = 75264;
constexpr int SMEM_DYN = SM_END + 1024 + 128;

// ---------------- launch 0: rbf + zero PA buffers ----------------
__global__ void rbf_kernel(const float* __restrict__ R,
                           const int* __restrict__ idx_i,
                           const int* __restrict__ idx_j,
                           float* __restrict__ rbf,
                           float* __restrict__ pa4)
{
    const float PI_F = 3.14159265358979323846f;
    const float c = sqrtf(2.f / 5.f);
    int gtid = blockIdx.x * blockDim.x + threadIdx.x;
    int gstr = gridDim.x * blockDim.x;
    size_t pn = (size_t)4*NA*128/4;
    float4 z = make_float4(0.f,0.f,0.f,0.f);
    for (size_t i = gtid; i < pn; i += gstr) ((float4*)pa4)[i] = z;
    for (int e = gtid; e < EG; e += gstr) {
        int i = idx_i[e], j = idx_j[e];
        float dx = R[3*i+0] - R[3*j+0];
        float dy = R[3*i+1] - R[3*j+1];
        float dz = R[3*i+2] - R[3*j+2];
        float d = sqrtf(dx*dx + dy*dy + dz*dz);
        d = fmaxf(d, 1e-2f);
        float inv = 1.f / d;
        float arg = d * (PI_F / 5.f);
        float s1, c1;
        __sincosf(arg, &s1, &c1);
        float tc = 2.f * c1;
        float sm1 = 0.f, s = s1;
        #pragma unroll
        for (int r = 0; r < NR; r++) {
            rbf[(size_t)e*NR + r] = c * s * inv;
            float nx = tc * s - sm1;
            sm1 = s; s = nx;
        }
    }
}

__global__ void x0_kernel(const int* __restrict__ Z,
                          const float* __restrict__ emb,
                          float* __restrict__ x0)
{
    size_t total = (size_t)NA * E;
    for (size_t idx = blockIdx.x * (size_t)blockDim.x + threadIdx.x; idx < total;
         idx += (size_t)gridDim.x * blockDim.x) {
        int a = (int)(idx >> 7);
        int c = (int)(idx & 127);
        x0[idx] = emb[(size_t)Z[a]*E + c];
    }
}

// coalesced buildcat: 128 threads = 2 edges x 64 column-pairs; u32 bf16x2 stores
__global__ __launch_bounds__(128) void buildcat_kernel(
    const int* __restrict__ Z,
    const int* __restrict__ idx_i,
    const int* __restrict__ idx_j,
    const float* __restrict__ emb,
    const float* __restrict__ Wrbf,
    const float* __restrict__ rbf,
    __nv_bfloat16* __restrict__ ch_,
    __nv_bfloat16* __restrict__ cl_)
{
    __shared__ float ws[NR*E];
    for (int k = threadIdx.x; k < NR*E; k += 128) ws[k] = Wrbf[k];
    __syncthreads();
    int half = threadIdx.x >> 6;
    int c2 = threadIdx.x & 63;
    int c0 = c2 * 2;
    for (int eb = blockIdx.x * 2; eb < EG; eb += gridDim.x * 2) {
        int e = eb + half;
        if (e >= EG) continue;
        int ai = idx_i[e], aj = idx_j[e];
        float r0 = rbf[(size_t)e*NR+0], r1 = rbf[(size_t)e*NR+1], r2 = rbf[(size_t)e*NR+2];
        float r3 = rbf[(size_t)e*NR+3], r4 = rbf[(size_t)e*NR+4], r5 = rbf[(size_t)e*NR+5];
        float s0 = r0*ws[c0]     + r1*ws[E+c0]     + r2*ws[2*E+c0]
                 + r3*ws[3*E+c0] + r4*ws[4*E+c0]   + r5*ws[5*E+c0];
        float s1 = r0*ws[c0+1]   + r1*ws[E+c0+1]   + r2*ws[2*E+c0+1]
                 + r3*ws[3*E+c0+1] + r4*ws[4*E+c0+1] + r5*ws[5*E+c0+1];
        s0 = silu_f(s0); s1 = silu_f(s1);
        float2 vi = *(const float2*)&emb[(size_t)Z[ai]*E + c0];
        float2 vj = *(const float2*)&emb[(size_t)Z[aj]*E + c0];
        size_t base = (size_t)e * 384;
        float l0, l1;
        uint32_t h;
        h = pack_bf16_hi(vi.x, vi.y, l0, l1);
        *(uint32_t*)&ch_[base + c0] = h;
        *(uint32_t*)&cl_[base + c0] = pack_bf16(l0, l1);
        h = pack_bf16_hi(vj.x, vj.y, l0, l1);
        *(uint32_t*)&ch_[base + 128 + c0] = h;
        *(uint32_t*)&cl_[base + 128 + c0] = pack_bf16(l0, l1);
        h = pack_bf16_hi(s0, s1, l0, l1);
        *(uint32_t*)&ch_[base + 256 + c0] = h;
        *(uint32_t*)&cl_[base + 256 + c0] = pack_bf16(l0, l1);
    }
}

// ---- batched transpose+split ----
struct TsplitJobs {
    const float* src[8];
    float* dst_h[8];
    float* dst_l[8];
    int K[8];
    int tot[8];
};
__global__ void tsplit_all_kernel(TsplitJobs jobs)
{
    int j = blockIdx.y;
    const float* s = jobs.src[j];
    __nv_bfloat16* h = (__nv_bfloat16*)jobs.dst_h[j];
    __nv_bfloat16* l = (__nv_bfloat16*)jobs.dst_l[j];
    int K = jobs.K[j];
    int tot = jobs.tot[j];
    int per = K * 128;
    for (int idx = blockIdx.x * blockDim.x + threadIdx.x; idx < tot;
         idx += gridDim.x * blockDim.x) {
        int b = idx / per;
        int rem = idx - b * per;
        int k = rem >> 7, n = rem & 127;
        float v = s[idx];
        __nv_bfloat16 hi = __float2bfloat16(v);
        float lo = v - __bfloat162float(hi);
        h[(size_t)b*per + (size_t)n*K + k] = hi;
        l[(size_t)b*per + (size_t)n*K + k] = __float2bfloat16(lo);
    }
}

// ---------------- mma.sync bf16x3 GEMM (R9-exact) ----------------
__global__ __launch_bounds__(256) void gemm_mma(
    const float* __restrict__ A,
    const __nv_bfloat16* __restrict__ A16h,
    const __nv_bfloat16* __restrict__ A16l,
    const __nv_bfloat16* __restrict__ Bh,
    const __nv_bfloat16* __restrict__ Bl,
    const float* __restrict__ bias,
    const float* __restrict__ mulW,
    const float* __restrict__ addp,
    const float* __restrict__ scW,
    const int* __restrict__ sc_idx, float* __restrict__ sc_out,
    const float* __restrict__ rbf,
    float* __restrict__ C,
    __nv_bfloat16* __restrict__ C16h,
    __nv_bfloat16* __restrict__ C16l,
    int M, int K, int act)
{
    extern __shared__ char smraw[];
    char* sm = (char*)(((uintptr_t)smraw + 1023) & ~(uintptr_t)1023);
    uint32_t smb = smem_u32(sm);
    float* wmul_s = (float*)(sm + SM_WMUL);
    float* wsc_s  = (float*)(sm + SM_WSC);
    float* rbf6   = (float*)(sm + SM_RBF6);
    float* bias_s = (float*)(sm + SM_BIAS);

    int tid = threadIdx.x;
    int lane = tid & 31;
    int wid = tid >> 5;
    int bm = blockIdx.x * 128;
    int need_rbf = (mulW != nullptr) || (scW != nullptr);

    for (int k = tid; k < NR*E; k += 256) {
        if (mulW) wmul_s[k] = mulW[k];
        if (scW)  wsc_s[k]  = scW[k];
    }
    for (int k = tid; k < E; k += 256) bias_s[k] = bias ? bias[k] : 0.f;
    if (need_rbf && tid < 128) {
        int g = bm + tid; if (g >= M) g = M - 1;
        #pragma unroll
        for (int q = 0; q < NR; q++) rbf6[tid*NR + q] = rbf[(size_t)g*NR + q];
    }
    __syncthreads();

    int wm = (wid & 3) * 32;
    int wn = (wid >> 2) * 64;
    int lq = lane >> 2;
    int lr4 = lane & 3;
    int r  = lane & 7;
    int mi = lane >> 3;
    uint32_t AHb = smb + SM_AH + (uint32_t)((wm + (mi&1)*8 + r) * 128);
    uint32_t ALb = AHb + TILE;
    int a_chsel = mi >> 1;
    uint32_t BHb = smb + SM_BH + (uint32_t)((wn + ((mi>>1)&1)*8 + r) * 128);
    uint32_t BLb = BHb + TILE;
    int b_chsel = mi & 1;

    float acc[2][8][4];
    #pragma unroll
    for (int a0 = 0; a0 < 2; a0++)
        #pragma unroll
        for (int b0 = 0; b0 < 8; b0++)
            #pragma unroll
            for (int c0 = 0; c0 < 4; c0++) acc[a0][b0][c0] = 0.f;

    int nch = K >> 6;
    for (int c = 0; c < nch; c++) {
        int kc = c << 6;

        #pragma unroll
        for (int u = 0; u < 8; u++) {
            int f = u*256 + tid;
            int which = f >> 10;
            int g2 = f & 1023;
            int n = g2 >> 3, ch = g2 & 7;
            const __nv_bfloat16* src = (which ? Bl : Bh) + (size_t)n*K + kc + ch*8;
            uint32_t dst = smb + (which ? SM_BL : SM_BH)
                         + (uint32_t)(n*128 + ((ch ^ (n & 7)) << 4));
            CP_ASYNC16(dst, src);
        }
        if (A16h) {
            #pragma unroll
            for (int u = 0; u < 8; u++) {
                int f = u*256 + tid;
                int which = f >> 10;
                int g2 = f & 1023;
                int rr = g2 >> 3, ch = g2 & 7;
                int g = bm + rr; if (g >= M) g = M - 1;
                const __nv_bfloat16* src = (which ? A16l : A16h) + (size_t)g*K + kc + ch*8;
                uint32_t dst = smb + (which ? SM_AL : SM_AH)
                             + (uint32_t)(rr*128 + ((ch ^ (rr & 7)) << 4));
                CP_ASYNC16(dst, src);
            }
            CP_COMMIT();
            CP_WAIT0();
        } else {
            CP_COMMIT();
            #pragma unroll
            for (int u = 0; u < 4; u++) {
                int f = u*256 + tid;
                int rr = f >> 3, ch = f & 7;
                int g = bm + rr;
                int k = kc + ch*8;
                float v[8];
                if (g < M) {
                    float4 p0 = *(const float4*)&A[(size_t)g*K + k];
                    float4 p1 = *(const float4*)&A[(size_t)g*K + k + 4];
                    v[0]=p0.x; v[1]=p0.y; v[2]=p0.z; v[3]=p0.w;
                    v[4]=p1.x; v[5]=p1.y; v[6]=p1.z; v[7]=p1.w;
                } else {
                    #pragma unroll
                    for (int e2 = 0; e2 < 8; e2++) v[e2] = 0.f;
                }
                uint4 hb, lb;
                float l0, l1;
                hb.x = pack_bf16_hi(v[0], v[1], l0, l1); lb.x = pack_bf16(l0, l1);
                hb.y = pack_bf16_hi(v[2], v[3], l0, l1); lb.y = pack_bf16(l0, l1);
                hb.z = pack_bf16_hi(v[4], v[5], l0, l1); lb.z = pack_bf16(l0, l1);
                hb.w = pack_bf16_hi(v[6], v[7], l0, l1); lb.w = pack_bf16(l0, l1);
                uint32_t sw = (uint32_t)(rr*128 + ((ch ^ (rr & 7)) << 4));
                *(uint4*)(sm + SM_AH + sw) = hb;
                *(uint4*)(sm + SM_AL + sw) = lb;
            }
            CP_WAIT0();
        }
        __syncthreads();

        #pragma unroll
        for (int ks = 0; ks < 4; ks++) {
            uint32_t aswz = (uint32_t)(((2*ks + a_chsel) ^ r) << 4);
            uint32_t bswz = (uint32_t)(((2*ks + b_chsel) ^ r) << 4);
            uint32_t ah[2][4], al[2][4];
            LDSM4(ah[0], AHb + aswz);
            LDSM4(ah[1], AHb + 2048 + aswz);
            LDSM4(al[0], ALb + aswz);
            LDSM4(al[1], ALb + 2048 + aswz);
            #pragma unroll
            for (int p = 0; p < 4; p++) {
                uint32_t bh[4], bl[4];
                LDSM4(bh, BHb + (uint32_t)(p*2048) + bswz);
                LDSM4(bl, BLb + (uint32_t)(p*2048) + bswz);
                #pragma unroll
                for (int mt = 0; mt < 2; mt++) {
                    MMA_BF16(acc[mt][2*p+0], ah[mt], bh[0], bh[1]);
                    MMA_BF16(acc[mt][2*p+0], ah[mt], bl[0], bl[1]);
                    MMA_BF16(acc[mt][2*p+0], al[mt], bh[0], bh[1]);
                    MMA_BF16(acc[mt][2*p+1], ah[mt], bh[2], bh[3]);
                    MMA_BF16(acc[mt][2*p+1], ah[mt], bl[2], bl[3]);
                    MMA_BF16(acc[mt][2*p+1], al[mt], bh[2], bh[3]);
                }
            }
        }
        __syncthreads();
    }

    #pragma unroll
    for (int mt = 0; mt < 2; mt++) {
        int lrbase = wm + mt*16 + lq;
        #pragma unroll
        for (int h = 0; h < 2; h++) {
            int lrow = lrbase + h*8;
            int row = bm + lrow;
            if (row >= M) continue;
            int asc = scW ? sc_idx[row] : 0;
            #pragma unroll
            for (int nt = 0; nt < 8; nt++) {
                int col = wn + nt*8 + lr4*2;
                float v0 = acc[mt][nt][2*h+0] + bias_s[col];
                float v1 = acc[mt][nt][2*h+1] + bias_s[col+1];
                if (act) { v0 = silu_f(v0); v1 = silu_f(v1); }
                if (mulW) {
                    float d0 = 0.f, d1 = 0.f;
                    #pragma unroll
                    for (int q = 0; q < NR; q++) {
                        float rq = rbf6[lrow*NR + q];
                        d0 += rq * wmul_s[q*E + col];
                        d1 += rq * wmul_s[q*E + col + 1];
                    }
                    v0 *= d0; v1 *= d1;
                }
                if (addp) {
                    float2 av = *(const float2*)&addp[(size_t)row*128 + col];
                    v0 += av.x; v1 += av.y;
                }
                if (C) *(float2*)&C[(size_t)row*128 + col] = make_float2(v0, v1);
                if (C16h) {
                    float l0, l1;
                    uint32_t hb = pack_bf16_hi(v0, v1, l0, l1);
                    uint32_t lb = pack_bf16(l0, l1);
                    *(uint32_t*)&C16h[(size_t)row*128 + col] = hb;
                    *(uint32_t*)&C16l[(size_t)row*128 + col] = lb;
                }
                if (scW) {
                    float g0 = 0.f, g1 = 0.f;
                    #pragma unroll
                    for (int q = 0; q < NR; q++) {
                        float rq = rbf6[lrow*NR + q];
                        g0 += rq * wsc_s[q*E + col];
                        g1 += rq * wsc_s[q*E + col + 1];
                    }
                    RED2(&sc_out[(size_t)asc*128 + col], g0*v0, g1*v1);
                }
            }
        }
    }
}

// ---------------- triplet messages + atomic scatter (unroll x2 for MLP) ----------------
__global__ __launch_bounds__(256) void triplet_kernel(
    const float* __restrict__ xkj,
    const float* __restrict__ cosik,
    const int* __restrict__ idx_kj,
    const int* __restrict__ idx_ji,
    const float* __restrict__ Wabf,       // [7,128]
    float* __restrict__ aggr)
{
    __shared__ float ws[NABF*E];
    for (int k = threadIdx.x; k < NABF*E; k += 256) ws[k] = Wabf[k];
    __syncthreads();
    int lane = threadIdx.x & 31;
    int warp = (blockIdx.x * 256 + threadIdx.x) >> 5;
    int nwarps = (gridDim.x * 256) >> 5;
    int c = lane << 2;
    // TT is even; process 2 triplets per iteration (2 outstanding gathers)
    for (int t = warp * 2; t < TT; t += nwarps * 2) {
        int ekj0 = idx_kj[t],   eji0 = idx_ji[t];
        int ekj1 = idx_kj[t+1], eji1 = idx_ji[t+1];
        float xa = fminf(1.f, fmaxf(-1.f, cosik[t]));
        float xb = fminf(1.f, fmaxf(-1.f, cosik[t+1]));
        float4 xv0 = *(const float4*)&xkj[(size_t)ekj0*128 + c];
        float4 xv1 = *(const float4*)&xkj[(size_t)ekj1*128 + c];
        // Chebyshev T_k for both
        float a1=xa, a2=2.f*xa*a1-1.f, a3=2.f*xa*a2-a1, a4=2.f*xa*a3-a2,
              a5=2.f*xa*a4-a3, a6=2.f*xa*a5-a4;
        float b1=xb, b2=2.f*xb*b1-1.f, b3=2.f*xb*b2-b1, b4=2.f*xb*b3-b2,
              b5=2.f*xb*b4-b3, b6=2.f*xb*b5-b4;
        float m0[4], m1[4];
        #pragma unroll
        for (int j = 0; j < 4; j++) {
            int cc = c + j;
            float w0=ws[cc], w1=ws[E+cc], w2=ws[2*E+cc], w3=ws[3*E+cc],
                  w4=ws[4*E+cc], w5=ws[5*E+cc], w6=ws[6*E+cc];
            m0[j] = w0 + a1*w1 + a2*w2 + a3*w3 + a4*w4 + a5*w5 + a6*w6;
            m1[j] = w0 + b1*w1 + b2*w2 + b3*w3 + b4*w4 + b5*w5 + b6*w6;
        }
        RED4(&aggr[(size_t)eji0*128 + c], xv0.x*m0[0], xv0.y*m0[1], xv0.z*m0[2], xv0.w*m0[3]);
        RED4(&aggr[(size_t)eji1*128 + c], xv1.x*m1[0], xv1.y*m1[1], xv1.z*m1[2], xv1.w*m1[3]);
    }
}

// ---------------- final molecule reduction ----------------
__global__ void final_kernel(const float* __restrict__ ro,
                             const float* __restrict__ rs,
                             const int* __restrict__ bseg,
                             const float* __restrict__ cmp_p,
                             const float* __restrict__ csg_p,
                             float* __restrict__ out)
{
    float cmp = cmp_p[0], csg = csg_p[0];
    size_t total = (size_t)NA * 32;
    for (size_t idx = blockIdx.x * (size_t)blockDim.x + threadIdx.x; idx < total;
         idx += (size_t)gridDim.x * blockDim.x) {
        int a = (int)(idx >> 5);
        int c = (int)(idx & 31) << 2;
        int m = bseg[a];
        float4 o = *(const float4*)&ro[(size_t)a*128 + c];
        float4 s = *(const float4*)&rs[(size_t)a*128 + c];
        RED4(&out[(size_t)m*128 + c],
             cmp*o.x + csg*s.x, cmp*o.y + csg*s.y,
             cmp*o.z + csg*s.z, cmp*o.w + csg*s.w);
    }
}

// ---------------- host orchestration (serial stream 0) ----------------
extern "C" void kernel_launch(void* const* d_in, const int* in_sizes, int n_in,
                              void* d_out, int out_size)
{
    const int*   Z      = (const int*)  d_in[0];
    const float* R      = (const float*)d_in[1];
    const int*   bseg   = (const int*)  d_in[2];
    const int*   idx_i  = (const int*)  d_in[3];
    const int*   idx_j  = (const int*)  d_in[4];
    const int*   idx_kj = (const int*)  d_in[5];
    const int*   idx_ji = (const int*)  d_in[6];
    const float* cosik  = (const float*)d_in[7];
    const float* emb    = (const float*)d_in[8];
    const float* Wrbf   = (const float*)d_in[9];
    const float* Wemb   = (const float*)d_in[10];
    const float* bemb   = (const float*)d_in[11];
    const float* Worbf  = (const float*)d_in[12];
    const float* Wo1    = (const float*)d_in[13];
    const float* bo1    = (const float*)d_in[14];
    const float* Wout   = (const float*)d_in[15];
    const float* Wid1   = (const float*)d_in[16];
    const float* bid1   = (const float*)d_in[17];
    const float* Wid2   = (const float*)d_in[18];
    const float* Wji    = (const float*)d_in[19];
    const float* bji    = (const float*)d_in[20];
    const float* Wkj    = (const float*)d_in[21];
    const float* bkj    = (const float*)d_in[22];
    const float* Wirbf  = (const float*)d_in[23];
    const float* Wabf   = (const float*)d_in[24];
    const float* Wres   = (const float*)d_in[25];
    const float* bres   = (const float*)d_in[26];
    const float* cmp    = (const float*)d_in[27];
    const float* csg    = (const float*)d_in[28];
    float* out = (float*)d_out;

    cudaFuncSetAttribute(gemm_mma, cudaFuncAttributeMaxDynamicSharedMemorySize, SMEM_DYN);

    float* buf = nullptr;
    cudaGetSymbolAddress((void**)&buf, g_buf);
    float* RBF   = buf + OFF_RBF;
    __nv_bfloat16* CATH = (__nv_bfloat16*)(buf + OFF_CATH);
    __nv_bfloat16* CATL = (__nv_bfloat16*)(buf + OFF_CATL);
    __nv_bfloat16* XH   = (__nv_bfloat16*)(buf + OFF_XH);
    __nv_bfloat16* XL   = (__nv_bfloat16*)(buf + OFF_XL);
    float* XKJ   = buf + OFF_XKJ;
    float* AGGR  = buf + OFF_AGGR;
    float* PA    = buf + OFF_PA;
    float* HAT   = buf + OFF_HAT;
    float* ROUT  = buf + OFF_ROUT;
    float* RSING = buf + OFF_RSING;
    float* STMP  = buf + OFF_STMP;
    float* X0    = buf + OFF_X0;
    float* WT    = buf + OFF_WT;

    #define BF(off) ((__nv_bfloat16*)(WT + (off)))
    #define PAB(b)  (PA + (size_t)(b)*NA*128)

    const int GE = (EG + 127) / 128;
    const int GA = (NA + 127) / 128;

    // launch 0: rbf + zero 4 PA buffers
    rbf_kernel<<<1024, 256>>>(R, idx_i, idx_j, RBF, PA);
    // launch 1: buildcat (needs only RBF)
    buildcat_kernel<<<4096, 128>>>(Z, idx_i, idx_j, emb, Wrbf, RBF, CATH, CATL);
    // launch 2: all weight splits
    {
        TsplitJobs j;
        j.src[0]=Wemb; j.dst_h[0]=(float*)BF(WT_EMB_H); j.dst_l[0]=(float*)BF(WT_EMB_L); j.K[0]=384; j.tot[0]=384*128;
        j.src[1]=Wo1;  j.dst_h[1]=(float*)BF(WT_O1_H);  j.dst_l[1]=(float*)BF(WT_O1_L);  j.K[1]=128; j.tot[1]=4*128*128;
        j.src[2]=Wout; j.dst_h[2]=(float*)BF(WT_OUT_H); j.dst_l[2]=(float*)BF(WT_OUT_L); j.K[2]=128; j.tot[2]=4*128*128;
        j.src[3]=Wid1; j.dst_h[3]=(float*)BF(WT_ID1_H); j.dst_l[3]=(float*)BF(WT_ID1_L); j.K[3]=128; j.tot[3]=4*128*128;
        j.src[4]=Wid2; j.dst_h[4]=(float*)BF(WT_ID2_H); j.dst_l[4]=(float*)BF(WT_ID2_L); j.K[4]=128; j.tot[4]=4*128*128;
        j.src[5]=Wji;  j.dst_h[5]=(float*)BF(WT_JI_H);  j.dst_l[5]=(float*)BF(WT_JI_L);  j.K[5]=128; j.tot[5]=3*128*128;
        j.src[6]=Wkj;  j.dst_h[6]=(float*)BF(WT_KJ_H);  j.dst_l[6]=(float*)BF(WT_KJ_L);  j.K[6]=128; j.tot[6]=3*128*128;
        j.src[7]=Wres; j.dst_h[7]=(float*)BF(WT_RES_H); j.dst_l[7]=(float*)BF(WT_RES_L); j.K[7]=128; j.tot[7]=3*128*128;
        tsplit_all_kernel<<<dim3(64, 8), 256>>>(j);
    }

    // launch 3: embedding GEMM  <-- ncu capture target (index 3)
    gemm_mma<<<GE, 256, SMEM_DYN>>>(nullptr, CATH, CATL,
                                    BF(WT_EMB_H), BF(WT_EMB_L), bemb,
                                    nullptr, nullptr,
                                    Worbf, idx_i, PAB(0), RBF,
                                    nullptr, XH, XL, EG, 384, 1);
    // launch 4: x0 gather (needed only by identity chain later)
    x0_kernel<<<1024, 256>>>(Z, emb, X0);

    for (int i = 0; i < NB; i++) {
        size_t wo = (size_t)i * 128 * 128;
        gemm_mma<<<GE, 256, SMEM_DYN>>>(nullptr, XH, XL,
                                        BF(WT_KJ_H) + wo, BF(WT_KJ_L) + wo, bkj + (size_t)i*E,
                                        Wirbf + (size_t)i*NR*E, nullptr,
                                        nullptr, nullptr, nullptr, RBF,
                                        XKJ, nullptr, nullptr, EG, 128, 1);
        gemm_mma<<<GE, 256, SMEM_DYN>>>(nullptr, XH, XL,
                                        BF(WT_JI_H) + wo, BF(WT_JI_L) + wo, bji + (size_t)i*E,
                                        nullptr, nullptr, nullptr, nullptr, nullptr, nullptr,
                                        AGGR, nullptr, nullptr, EG, 128, 1);
        triplet_kernel<<<2048, 256>>>(XKJ, cosik, idx_kj, idx_ji,
                                      Wabf + (size_t)i*NABF*E, AGGR);
        gemm_mma<<<GE, 256, SMEM_DYN>>>(AGGR, nullptr, nullptr,
                                        BF(WT_RES_H) + wo, BF(WT_RES_L) + wo, bres + (size_t)i*E,
                                        nullptr, AGGR,
                                        Worbf + (size_t)(i+1)*NR*E, idx_i, PAB(i+1), RBF,
                                        nullptr, XH, XL, EG, 128, 1);
    }

    // output chains (blocks 0..3)
    for (int b = 0; b <= NB; b++) {
        size_t wo1 = (size_t)b * 128 * 128;
        gemm_mma<<<GA, 256, SMEM_DYN>>>(PAB(b), nullptr, nullptr,
                                        BF(WT_O1_H) + wo1, BF(WT_O1_L) + wo1, bo1 + (size_t)b*E,
                                        nullptr, nullptr, nullptr, nullptr, nullptr, nullptr,
                                        HAT, nullptr, nullptr, NA, 128, 1);
        gemm_mma<<<GA, 256, SMEM_DYN>>>(HAT, nullptr, nullptr,
                                        BF(WT_OUT_H) + wo1, BF(WT_OUT_L) + wo1, nullptr,
                                        nullptr, (b == 0) ? nullptr : ROUT,
                                        nullptr, nullptr, nullptr, nullptr,
                                        ROUT, nullptr, nullptr, NA, 128, 0);
    }

    // identity chain
    gemm_mma<<<GA, 256, SMEM_DYN>>>(X0, nullptr, nullptr, BF(WT_ID1_H), BF(WT_ID1_L), bid1,
                                    nullptr, nullptr, nullptr, nullptr, nullptr, nullptr,
                                    STMP, nullptr, nullptr, NA, 128, 1);
    gemm_mma<<<GA, 256, SMEM_DYN>>>(STMP, nullptr, nullptr, BF(WT_ID2_H), BF(WT_ID2_L), nullptr,
                                    nullptr, nullptr, nullptr, nullptr, nullptr, nullptr,
                                    RSING, nullptr, nullptr, NA, 128, 0);
    for (int b = 1; b <= NB; b++) {
        size_t wo1 = (size_t)b * 128 * 128;
        gemm_mma<<<GA, 256, SMEM_DYN>>>(RSING, nullptr, nullptr,
                                        BF(WT_ID1_H) + wo1, BF(WT_ID1_L) + wo1, bid1 + (size_t)b*E,
                                        nullptr, nullptr, nullptr, nullptr, nullptr, nullptr,
                                        STMP, nullptr, nullptr, NA, 128, 1);
        gemm_mma<<<GA, 256, SMEM_DYN>>>(STMP, nullptr, nullptr,
                                        BF(WT_ID2_H) + wo1, BF(WT_ID2_L) + wo1, nullptr,
                                        nullptr, RSING, nullptr, nullptr, nullptr, nullptr,
                                        RSING, nullptr, nullptr, NA, 128, 0);
    }

    // final
    cudaMemsetAsync(out, 0, (size_t)NM*E*sizeof(float));
    final_kernel<<<512, 256>>>(ROUT, RSING, bseg, cmp, csg, out);
}

// round 15
// speedup vs baseline: 1.1089x; 1.0504x over previous
#include <cuda_runtime.h>
#include <cuda_bf16.h>
#include <cstdint>
#include <cstddef>
#include <math.h>

// ---------------- problem constants ----------------
constexpr int EG  = 300000;   // edges
constexpr int TT  = 1000000;  // triplets
constexpr int NA  = 20000;    // atoms
constexpr int NM  = 1000;     // molecules
constexpr int E   = 128;      // embedding
constexpr int NR  = 6;
constexpr int NABF= 7;
constexpr int NB  = 3;

// ---------------- scratch layout (float granules) ----------------
constexpr size_t OFF_RBF  = 0;                                    // EG*6 f32
constexpr size_t OFF_CATH = OFF_RBF  + (size_t)EG*6;              // bf16[EG][384]
constexpr size_t OFF_CATL = OFF_CATH + (size_t)EG*192;
constexpr size_t OFF_XH   = OFF_CATL + (size_t)EG*192;            // bf16[EG][128]
constexpr size_t OFF_XL   = OFF_XH   + (size_t)EG*64;
constexpr size_t OFF_XKJ  = OFF_XL   + (size_t)EG*64;             // f32[EG][128]
constexpr size_t OFF_AGGR = OFF_XKJ  + (size_t)EG*128;
constexpr size_t OFF_PA   = OFF_AGGR + (size_t)EG*128;            // 4 x f32[NA][128]
constexpr size_t OFF_HAT  = OFF_PA   + (size_t)4*NA*128;
constexpr size_t OFF_ROUT = OFF_HAT  + (size_t)NA*128;
constexpr size_t OFF_RSING= OFF_ROUT + (size_t)NA*128;
constexpr size_t OFF_STMP = OFF_RSING+ (size_t)NA*128;
constexpr size_t OFF_X0   = OFF_STMP + (size_t)NA*128;
constexpr size_t OFF_WT   = OFF_X0   + (size_t)NA*128;
// inside WT (bf16 element offsets relative to BF(base))
constexpr size_t WT_EMB_H = 0;
constexpr size_t WT_EMB_L = 49152;
constexpr size_t WT_O1_H  = 98304;
constexpr size_t WT_O1_L  = 163840;
constexpr size_t WT_OUT_H = 229376;
constexpr size_t WT_OUT_L = 294912;
constexpr size_t WT_ID1_H = 360448;
constexpr size_t WT_ID1_L = 425984;
constexpr size_t WT_ID2_H = 491520;
constexpr size_t WT_ID2_L = 557056;
constexpr size_t WT_JI_H  = 622592;
constexpr size_t WT_JI_L  = 671744;
constexpr size_t WT_KJ_H  = 720896;
constexpr size_t WT_KJ_L  = 770048;
constexpr size_t WT_RES_H = 819200;
constexpr size_t WT_RES_L = 868352;
constexpr size_t WT_TOTAL = 917504;
constexpr size_t TOTAL_F  = OFF_WT + WT_TOTAL;

__device__ float g_buf[TOTAL_F];

// ---------------- helpers ----------------
__device__ __forceinline__ uint32_t smem_u32(const void* p) {
    uint32_t a;
    asm("{ .reg .u64 t; cvta.to.shared.u64 t, %1; cvt.u32.u64 %0, t; }" : "=r"(a) : "l"(p));
    return a;
}
__device__ __forceinline__ float silu_f(float x) { return x / (1.f + __expf(-x)); }

#define LDSM4(rr, addr) \
    asm volatile("ldmatrix.sync.aligned.m8n8.x4.shared.b16 {%0,%1,%2,%3}, [%4];" \
        : "=r"((rr)[0]), "=r"((rr)[1]), "=r"((rr)[2]), "=r"((rr)[3]) : "r"(addr))

#define MMA_BF16(d, a, b0, b1) \
    asm volatile("mma.sync.aligned.m16n8k16.row.col.f32.bf16.bf16.f32 " \
        "{%0,%1,%2,%3},{%4,%5,%6,%7},{%8,%9},{%0,%1,%2,%3};" \
        : "+f"((d)[0]), "+f"((d)[1]), "+f"((d)[2]), "+f"((d)[3]) \
        : "r"((a)[0]), "r"((a)[1]), "r"((a)[2]), "r"((a)[3]), "r"(b0), "r"(b1))

#define CP_ASYNC16(dst, src) \
    asm volatile("cp.async.cg.shared.global [%0], [%1], 16;" :: "r"(dst), "l"(src) : "memory")
#define CP_COMMIT() asm volatile("cp.async.commit_group;" ::: "memory")
#define CP_WAIT0()  asm volatile("cp.async.wait_group 0;" ::: "memory")

#define RED4(ptr, a, b, c, dd) \
    asm volatile("red.global.add.v4.f32 [%0], {%1,%2,%3,%4};" \
        :: "l"(ptr), "f"(a), "f"(b), "f"(c), "f"(dd) : "memory")
#define RED2(ptr, a, b) \
    asm volatile("red.global.add.v2.f32 [%0], {%1,%2};" \
        :: "l"(ptr), "f"(a), "f"(b) : "memory")

__device__ __forceinline__ uint32_t pack_bf16_hi(float a, float b, float& la, float& lb) {
    __nv_bfloat162 h = __floats2bfloat162_rn(a, b);
    la = a - __bfloat162float(h.x);
    lb = b - __bfloat162float(h.y);
    return *(uint32_t*)&h;
}
__device__ __forceinline__ uint32_t pack_bf16(float a, float b) {
    __nv_bfloat162 h = __floats2bfloat162_rn(a, b);
    return *(uint32_t*)&h;
}

// ---------------- smem layout (bytes after 1024-align) ----------------
// double-buffered: 2 stages x (AH | AL | BH | BL), each tile 16 KB
constexpr int TILE   = 16384;
constexpr int STAGE  = 4 * TILE;        // 65536
constexpr int SM_AH  = 0;               // within stage
constexpr int SM_AL  = TILE;
constexpr int SM_BH  = 2 * TILE;
constexpr int SM_BL  = 3 * TILE;
constexpr int SM_WMUL = 2 * STAGE;      // 131072
constexpr int SM_WSC  = SM_WMUL + 3072;
constexpr int SM_RBF6 = SM_WSC + 3072;
constexpr int SM_BIAS = SM_RBF6 + 3072;
constexpr int SM_END  = SM_BIAS + 512;
constexpr int SMEM_DYN = SM_END + 1024 + 128;

// ---------------- launch 0: rbf + zero PA buffers ----------------
__global__ void rbf_kernel(const float* __restrict__ R,
                           const int* __restrict__ idx_i,
                           const int* __restrict__ idx_j,
                           float* __restrict__ rbf,
                           float* __restrict__ pa4)
{
    const float PI_F = 3.14159265358979323846f;
    const float c = sqrtf(2.f / 5.f);
    int gtid = blockIdx.x * blockDim.x + threadIdx.x;
    int gstr = gridDim.x * blockDim.x;
    size_t pn = (size_t)4*NA*128/4;
    float4 z = make_float4(0.f,0.f,0.f,0.f);
    for (size_t i = gtid; i < pn; i += gstr) ((float4*)pa4)[i] = z;
    for (int e = gtid; e < EG; e += gstr) {
        int i = idx_i[e], j = idx_j[e];
        float dx = R[3*i+0] - R[3*j+0];
        float dy = R[3*i+1] - R[3*j+1];
        float dz = R[3*i+2] - R[3*j+2];
        float d = sqrtf(dx*dx + dy*dy + dz*dz);
        d = fmaxf(d, 1e-2f);
        float inv = 1.f / d;
        float arg = d * (PI_F / 5.f);
        float s1, c1;
        __sincosf(arg, &s1, &c1);
        float tc = 2.f * c1;
        float sm1 = 0.f, s = s1;
        #pragma unroll
        for (int r = 0; r < NR; r++) {
            rbf[(size_t)e*NR + r] = c * s * inv;
            float nx = tc * s - sm1;
            sm1 = s; s = nx;
        }
    }
}

__global__ void x0_kernel(const int* __restrict__ Z,
                          const float* __restrict__ emb,
                          float* __restrict__ x0)
{
    size_t total = (size_t)NA * E;
    for (size_t idx = blockIdx.x * (size_t)blockDim.x + threadIdx.x; idx < total;
         idx += (size_t)gridDim.x * blockDim.x) {
        int a = (int)(idx >> 7);
        int c = (int)(idx & 127);
        x0[idx] = emb[(size_t)Z[a]*E + c];
    }
}

// coalesced buildcat
__global__ __launch_bounds__(128) void buildcat_kernel(
    const int* __restrict__ Z,
    const int* __restrict__ idx_i,
    const int* __restrict__ idx_j,
    const float* __restrict__ emb,
    const float* __restrict__ Wrbf,
    const float* __restrict__ rbf,
    __nv_bfloat16* __restrict__ ch_,
    __nv_bfloat16* __restrict__ cl_)
{
    __shared__ float ws[NR*E];
    for (int k = threadIdx.x; k < NR*E; k += 128) ws[k] = Wrbf[k];
    __syncthreads();
    int half = threadIdx.x >> 6;
    int c2 = threadIdx.x & 63;
    int c0 = c2 * 2;
    for (int eb = blockIdx.x * 2; eb < EG; eb += gridDim.x * 2) {
        int e = eb + half;
        if (e >= EG) continue;
        int ai = idx_i[e], aj = idx_j[e];
        float r0 = rbf[(size_t)e*NR+0], r1 = rbf[(size_t)e*NR+1], r2 = rbf[(size_t)e*NR+2];
        float r3 = rbf[(size_t)e*NR+3], r4 = rbf[(size_t)e*NR+4], r5 = rbf[(size_t)e*NR+5];
        float s0 = r0*ws[c0]     + r1*ws[E+c0]     + r2*ws[2*E+c0]
                 + r3*ws[3*E+c0] + r4*ws[4*E+c0]   + r5*ws[5*E+c0];
        float s1 = r0*ws[c0+1]   + r1*ws[E+c0+1]   + r2*ws[2*E+c0+1]
                 + r3*ws[3*E+c0+1] + r4*ws[4*E+c0+1] + r5*ws[5*E+c0+1];
        s0 = silu_f(s0); s1 = silu_f(s1);
        float2 vi = *(const float2*)&emb[(size_t)Z[ai]*E + c0];
        float2 vj = *(const float2*)&emb[(size_t)Z[aj]*E + c0];
        size_t base = (size_t)e * 384;
        float l0, l1;
        uint32_t h;
        h = pack_bf16_hi(vi.x, vi.y, l0, l1);
        *(uint32_t*)&ch_[base + c0] = h;
        *(uint32_t*)&cl_[base + c0] = pack_bf16(l0, l1);
        h = pack_bf16_hi(vj.x, vj.y, l0, l1);
        *(uint32_t*)&ch_[base + 128 + c0] = h;
        *(uint32_t*)&cl_[base + 128 + c0] = pack_bf16(l0, l1);
        h = pack_bf16_hi(s0, s1, l0, l1);
        *(uint32_t*)&ch_[base + 256 + c0] = h;
        *(uint32_t*)&cl_[base + 256 + c0] = pack_bf16(l0, l1);
    }
}

// ---- batched transpose+split ----
struct TsplitJobs {
    const float* src[8];
    float* dst_h[8];
    float* dst_l[8];
    int K[8];
    int tot[8];
};
__global__ void tsplit_all_kernel(TsplitJobs jobs)
{
    int j = blockIdx.y;
    const float* s = jobs.src[j];
    __nv_bfloat16* h = (__nv_bfloat16*)jobs.dst_h[j];
    __nv_bfloat16* l = (__nv_bfloat16*)jobs.dst_l[j];
    int K = jobs.K[j];
    int tot = jobs.tot[j];
    int per = K * 128;
    for (int idx = blockIdx.x * blockDim.x + threadIdx.x; idx < tot;
         idx += gridDim.x * blockDim.x) {
        int b = idx / per;
        int rem = idx - b * per;
        int k = rem >> 7, n = rem & 127;
        float v = s[idx];
        __nv_bfloat16 hi = __float2bfloat16(v);
        float lo = v - __bfloat162float(hi);
        h[(size_t)b*per + (size_t)n*K + k] = hi;
        l[(size_t)b*per + (size_t)n*K + k] = __float2bfloat16(lo);
    }
}

// ---------------- mma.sync bf16x3 GEMM, canonical 2-stage pipeline ----------------
__global__ __launch_bounds__(256) void gemm_mma(
    const float* __restrict__ A,
    const __nv_bfloat16* __restrict__ A16h,
    const __nv_bfloat16* __restrict__ A16l,
    const __nv_bfloat16* __restrict__ Bh,
    const __nv_bfloat16* __restrict__ Bl,
    const float* __restrict__ bias,
    const float* __restrict__ mulW,
    const float* __restrict__ addp,
    const float* __restrict__ scW,
    const int* __restrict__ sc_idx, float* __restrict__ sc_out,
    const float* __restrict__ rbf,
    float* __restrict__ C,
    __nv_bfloat16* __restrict__ C16h,
    __nv_bfloat16* __restrict__ C16l,
    int M, int K, int act)
{
    extern __shared__ char smraw[];
    char* sm = (char*)(((uintptr_t)smraw + 1023) & ~(uintptr_t)1023);
    uint32_t smb = smem_u32(sm);
    float* wmul_s = (float*)(sm + SM_WMUL);
    float* wsc_s  = (float*)(sm + SM_WSC);
    float* rbf6   = (float*)(sm + SM_RBF6);
    float* bias_s = (float*)(sm + SM_BIAS);

    int tid = threadIdx.x;
    int lane = tid & 31;
    int wid = tid >> 5;
    int bm = blockIdx.x * 128;
    int need_rbf = (mulW != nullptr) || (scW != nullptr);

    for (int k = tid; k < NR*E; k += 256) {
        if (mulW) wmul_s[k] = mulW[k];
        if (scW)  wsc_s[k]  = scW[k];
    }
    for (int k = tid; k < E; k += 256) bias_s[k] = bias ? bias[k] : 0.f;
    if (need_rbf && tid < 128) {
        int g = bm + tid; if (g >= M) g = M - 1;
        #pragma unroll
        for (int q = 0; q < NR; q++) rbf6[tid*NR + q] = rbf[(size_t)g*NR + q];
    }
    __syncthreads();

    int wm = (wid & 3) * 32;
    int wn = (wid >> 2) * 64;
    int lq = lane >> 2;
    int lr4 = lane & 3;
    int r  = lane & 7;
    int mi = lane >> 3;
    uint32_t AHb = smb + SM_AH + (uint32_t)((wm + (mi&1)*8 + r) * 128);
    int a_chsel = mi >> 1;
    uint32_t BHb = smb + SM_BH + (uint32_t)((wn + ((mi>>1)&1)*8 + r) * 128);
    int b_chsel = mi & 1;

    float acc[2][8][4];
    #pragma unroll
    for (int a0 = 0; a0 < 2; a0++)
        #pragma unroll
        for (int b0 = 0; b0 < 8; b0++)
            #pragma unroll
            for (int c0 = 0; c0 < 4; c0++) acc[a0][b0][c0] = 0.f;

    int nch = K >> 6;

    // loader for chunk cc into stage cc&1
    auto load_chunk = [&](int cc) {
        int kc = cc << 6;
        uint32_t sb = smb + (uint32_t)(cc & 1) * STAGE;
        char* sp = sm + (cc & 1) * STAGE;
        #pragma unroll
        for (int u = 0; u < 8; u++) {
            int f = u*256 + tid;
            int which = f >> 10;
            int g2 = f & 1023;
            int n = g2 >> 3, ch = g2 & 7;
            const __nv_bfloat16* src = (which ? Bl : Bh) + (size_t)n*K + kc + ch*8;
            uint32_t dst = sb + (which ? SM_BL : SM_BH)
                         + (uint32_t)(n*128 + ((ch ^ (n & 7)) << 4));
            CP_ASYNC16(dst, src);
        }
        if (A16h) {
            #pragma unroll
            for (int u = 0; u < 8; u++) {
                int f = u*256 + tid;
                int which = f >> 10;
                int g2 = f & 1023;
                int rr = g2 >> 3, ch = g2 & 7;
                int g = bm + rr; if (g >= M) g = M - 1;
                const __nv_bfloat16* src = (which ? A16l : A16h) + (size_t)g*K + kc + ch*8;
                uint32_t dst = sb + (which ? SM_AL : SM_AH)
                             + (uint32_t)(rr*128 + ((ch ^ (rr & 7)) << 4));
                CP_ASYNC16(dst, src);
            }
        } else {
            #pragma unroll
            for (int u = 0; u < 4; u++) {
                int f = u*256 + tid;
                int rr = f >> 3, ch = f & 7;
                int g = bm + rr;
                int k = kc + ch*8;
                float v[8];
                if (g < M) {
                    float4 p0 = *(const float4*)&A[(size_t)g*K + k];
                    float4 p1 = *(const float4*)&A[(size_t)g*K + k + 4];
                    v[0]=p0.x; v[1]=p0.y; v[2]=p0.z; v[3]=p0.w;
                    v[4]=p1.x; v[5]=p1.y; v[6]=p1.z; v[7]=p1.w;
                } else {
                    #pragma unroll
                    for (int e2 = 0; e2 < 8; e2++) v[e2] = 0.f;
                }
                uint4 hb, lb;
                float l0, l1;
                hb.x = pack_bf16_hi(v[0], v[1], l0, l1); lb.x = pack_bf16(l0, l1);
                hb.y = pack_bf16_hi(v[2], v[3], l0, l1); lb.y = pack_bf16(l0, l1);
                hb.z = pack_bf16_hi(v[4], v[5], l0, l1); lb.z = pack_bf16(l0, l1);
                hb.w = pack_bf16_hi(v[6], v[7], l0, l1); lb.w = pack_bf16(l0, l1);
                uint32_t sw = (uint32_t)(rr*128 + ((ch ^ (rr & 7)) << 4));
                *(uint4*)(sp + SM_AH + sw) = hb;
                *(uint4*)(sp + SM_AL + sw) = lb;
            }
        }
        CP_COMMIT();
    };

    load_chunk(0);
    for (int c = 0; c < nch; c++) {
        CP_WAIT0();              // chunk c's group complete (only group pending)
        __syncthreads();         // chunk c fully visible to all threads
        if (c + 1 < nch)
            load_chunk(c + 1);   // async fill of other stage; overlaps compute below
        uint32_t so = (uint32_t)(c & 1) * STAGE;
        #pragma unroll
        for (int ks = 0; ks < 4; ks++) {
            uint32_t aswz = (uint32_t)(((2*ks + a_chsel) ^ r) << 4);
            uint32_t bswz = (uint32_t)(((2*ks + b_chsel) ^ r) << 4);
            uint32_t ah[2][4], al[2][4];
            LDSM4(ah[0], AHb + so + aswz);
            LDSM4(ah[1], AHb + so + 2048 + aswz);
            LDSM4(al[0], AHb + so + TILE + aswz);
            LDSM4(al[1], AHb + so + TILE + 2048 + aswz);
            #pragma unroll
            for (int p = 0; p < 4; p++) {
                uint32_t bh[4], bl[4];
                LDSM4(bh, BHb + so + (uint32_t)(p*2048) + bswz);
                LDSM4(bl, BHb + so + TILE + (uint32_t)(p*2048) + bswz);
                #pragma unroll
                for (int mt = 0; mt < 2; mt++) {
                    MMA_BF16(acc[mt][2*p+0], ah[mt], bh[0], bh[1]);
                    MMA_BF16(acc[mt][2*p+0], ah[mt], bl[0], bl[1]);
                    MMA_BF16(acc[mt][2*p+0], al[mt], bh[0], bh[1]);
                    MMA_BF16(acc[mt][2*p+1], ah[mt], bh[2], bh[3]);
                    MMA_BF16(acc[mt][2*p+1], ah[mt], bl[2], bl[3]);
                    MMA_BF16(acc[mt][2*p+1], al[mt], bh[2], bh[3]);
                }
            }
        }
        __syncthreads();         // all reads of stage c&1 done before it is refilled
    }

    // ---- epilogue (R9-exact) ----
    #pragma unroll
    for (int mt = 0; mt < 2; mt++) {
        int lrbase = wm + mt*16 + lq;
        #pragma unroll
        for (int h = 0; h < 2; h++) {
            int lrow = lrbase + h*8;
            int row = bm + lrow;
            if (row >= M) continue;
            int asc = scW ? sc_idx[row] : 0;
            #pragma unroll
            for (int nt = 0; nt < 8; nt++) {
                int col = wn + nt*8 + lr4*2;
                float v0 = acc[mt][nt][2*h+0] + bias_s[col];
                float v1 = acc[mt][nt][2*h+1] + bias_s[col+1];
                if (act) { v0 = silu_f(v0); v1 = silu_f(v1); }
                if (mulW) {
                    float d0 = 0.f, d1 = 0.f;
                    #pragma unroll
                    for (int q = 0; q < NR; q++) {
                        float rq = rbf6[lrow*NR + q];
                        d0 += rq * wmul_s[q*E + col];
                        d1 += rq * wmul_s[q*E + col + 1];
                    }
                    v0 *= d0; v1 *= d1;
                }
                if (addp) {
                    float2 av = *(const float2*)&addp[(size_t)row*128 + col];
                    v0 += av.x; v1 += av.y;
                }
                if (C) *(float2*)&C[(size_t)row*128 + col] = make_float2(v0, v1);
                if (C16h) {
                    float l0, l1;
                    uint32_t hb = pack_bf16_hi(v0, v1, l0, l1);
                    uint32_t lb = pack_bf16(l0, l1);
                    *(uint32_t*)&C16h[(size_t)row*128 + col] = hb;
                    *(uint32_t*)&C16l[(size_t)row*128 + col] = lb;
                }
                if (scW) {
                    float g0 = 0.f, g1 = 0.f;
                    #pragma unroll
                    for (int q = 0; q < NR; q++) {
                        float rq = rbf6[lrow*NR + q];
                        g0 += rq * wsc_s[q*E + col];
                        g1 += rq * wsc_s[q*E + col + 1];
                    }
                    RED2(&sc_out[(size_t)asc*128 + col], g0*v0, g1*v1);
                }
            }
        }
    }
}

// ---------------- triplet messages + atomic scatter (unroll x2) ----------------
__global__ __launch_bounds__(256) void triplet_kernel(
    const float* __restrict__ xkj,
    const float* __restrict__ cosik,
    const int* __restrict__ idx_kj,
    const int* __restrict__ idx_ji,
    const float* __restrict__ Wabf,       // [7,128]
    float* __restrict__ aggr)
{
    __shared__ float ws[NABF*E];
    for (int k = threadIdx.x; k < NABF*E; k += 256) ws[k] = Wabf[k];
    __syncthreads();
    int lane = threadIdx.x & 31;
    int warp = (blockIdx.x * 256 + threadIdx.x) >> 5;
    int nwarps = (gridDim.x * 256) >> 5;
    int c = lane << 2;
    for (int t = warp * 2; t < TT; t += nwarps * 2) {
        int ekj0 = idx_kj[t],   eji0 = idx_ji[t];
        int ekj1 = idx_kj[t+1], eji1 = idx_ji[t+1];
        float xa = fminf(1.f, fmaxf(-1.f, cosik[t]));
        float xb = fminf(1.f, fmaxf(-1.f, cosik[t+1]));
        float4 xv0 = *(const float4*)&xkj[(size_t)ekj0*128 + c];
        float4 xv1 = *(const float4*)&xkj[(size_t)ekj1*128 + c];
        float a1=xa, a2=2.f*xa*a1-1.f, a3=2.f*xa*a2-a1, a4=2.f*xa*a3-a2,
              a5=2.f*xa*a4-a3, a6=2.f*xa*a5-a4;
        float b1=xb, b2=2.f*xb*b1-1.f, b3=2.f*xb*b2-b1, b4=2.f*xb*b3-b2,
              b5=2.f*xb*b4-b3, b6=2.f*xb*b5-b4;
        float m0[4], m1[4];
        #pragma unroll
        for (int j = 0; j < 4; j++) {
            int cc = c + j;
            float w0=ws[cc], w1=ws[E+cc], w2=ws[2*E+cc], w3=ws[3*E+cc],
                  w4=ws[4*E+cc], w5=ws[5*E+cc], w6=ws[6*E+cc];
            m0[j] = w0 + a1*w1 + a2*w2 + a3*w3 + a4*w4 + a5*w5 + a6*w6;
            m1[j] = w0 + b1*w1 + b2*w2 + b3*w3 + b4*w4 + b5*w5 + b6*w6;
        }
        RED4(&aggr[(size_t)eji0*128 + c], xv0.x*m0[0], xv0.y*m0[1], xv0.z*m0[2], xv0.w*m0[3]);
        RED4(&aggr[(size_t)eji1*128 + c], xv1.x*m1[0], xv1.y*m1[1], xv1.z*m1[2], xv1.w*m1[3]);
    }
}

// ---------------- final molecule reduction ----------------
__global__ void final_kernel(const float* __restrict__ ro,
                             const float* __restrict__ rs,
                             const int* __restrict__ bseg,
                             const float* __restrict__ cmp_p,
                             const float* __restrict__ csg_p,
                             float* __restrict__ out)
{
    float cmp = cmp_p[0], csg = csg_p[0];
    size_t total = (size_t)NA * 32;
    for (size_t idx = blockIdx.x * (size_t)blockDim.x + threadIdx.x; idx < total;
         idx += (size_t)gridDim.x * blockDim.x) {
        int a = (int)(idx >> 5);
        int c = (int)(idx & 31) << 2;
        int m = bseg[a];
        float4 o = *(const float4*)&ro[(size_t)a*128 + c];
        float4 s = *(const float4*)&rs[(size_t)a*128 + c];
        RED4(&out[(size_t)m*128 + c],
             cmp*o.x + csg*s.x, cmp*o.y + csg*s.y,
             cmp*o.z + csg*s.z, cmp*o.w + csg*s.w);
    }
}

// ---------------- host orchestration (serial stream 0) ----------------
extern "C" void kernel_launch(void* const* d_in, const int* in_sizes, int n_in,
                              void* d_out, int out_size)
{
    const int*   Z      = (const int*)  d_in[0];
    const float* R      = (const float*)d_in[1];
    const int*   bseg   = (const int*)  d_in[2];
    const int*   idx_i  = (const int*)  d_in[3];
    const int*   idx_j  = (const int*)  d_in[4];
    const int*   idx_kj = (const int*)  d_in[5];
    const int*   idx_ji = (const int*)  d_in[6];
    const float* cosik  = (const float*)d_in[7];
    const float* emb    = (const float*)d_in[8];
    const float* Wrbf   = (const float*)d_in[9];
    const float* Wemb   = (const float*)d_in[10];
    const float* bemb   = (const float*)d_in[11];
    const float* Worbf  = (const float*)d_in[12];
    const float* Wo1    = (const float*)d_in[13];
    const float* bo1    = (const float*)d_in[14];
    const float* Wout   = (const float*)d_in[15];
    const float* Wid1   = (const float*)d_in[16];
    const float* bid1   = (const float*)d_in[17];
    const float* Wid2   = (const float*)d_in[18];
    const float* Wji    = (const float*)d_in[19];
    const float* bji    = (const float*)d_in[20];
    const float* Wkj    = (const float*)d_in[21];
    const float* bkj    = (const float*)d_in[22];
    const float* Wirbf  = (const float*)d_in[23];
    const float* Wabf   = (const float*)d_in[24];
    const float* Wres   = (const float*)d_in[25];
    const float* bres   = (const float*)d_in[26];
    const float* cmp    = (const float*)d_in[27];
    const float* csg    = (const float*)d_in[28];
    float* out = (float*)d_out;

    cudaFuncSetAttribute(gemm_mma, cudaFuncAttributeMaxDynamicSharedMemorySize, SMEM_DYN);

    float* buf = nullptr;
    cudaGetSymbolAddress((void**)&buf, g_buf);
    float* RBF   = buf + OFF_RBF;
    __nv_bfloat16* CATH = (__nv_bfloat16*)(buf + OFF_CATH);
    __nv_bfloat16* CATL = (__nv_bfloat16*)(buf + OFF_CATL);
    __nv_bfloat16* XH   = (__nv_bfloat16*)(buf + OFF_XH);
    __nv_bfloat16* XL   = (__nv_bfloat16*)(buf + OFF_XL);
    float* XKJ   = buf + OFF_XKJ;
    float* AGGR  = buf + OFF_AGGR;
    float* PA    = buf + OFF_PA;
    float* HAT   = buf + OFF_HAT;
    float* ROUT  = buf + OFF_ROUT;
    float* RSING = buf + OFF_RSING;
    float* STMP  = buf + OFF_STMP;
    float* X0    = buf + OFF_X0;
    float* WT    = buf + OFF_WT;

    #define BF(off) ((__nv_bfloat16*)(WT + (off)))
    #define PAB(b)  (PA + (size_t)(b)*NA*128)

    const int GE = (EG + 127) / 128;
    const int GA = (NA + 127) / 128;

    // launch 0: rbf + zero 4 PA buffers
    rbf_kernel<<<1024, 256>>>(R, idx_i, idx_j, RBF, PA);
    // launch 1: buildcat
    buildcat_kernel<<<4096, 128>>>(Z, idx_i, idx_j, emb, Wrbf, RBF, CATH, CATL);
    // launch 2: all weight splits
    {
        TsplitJobs j;
        j.src[0]=Wemb; j.dst_h[0]=(float*)BF(WT_EMB_H); j.dst_l[0]=(float*)BF(WT_EMB_L); j.K[0]=384; j.tot[0]=384*128;
        j.src[1]=Wo1;  j.dst_h[1]=(float*)BF(WT_O1_H);  j.dst_l[1]=(float*)BF(WT_O1_L);  j.K[1]=128; j.tot[1]=4*128*128;
        j.src[2]=Wout; j.dst_h[2]=(float*)BF(WT_OUT_H); j.dst_l[2]=(float*)BF(WT_OUT_L); j.K[2]=128; j.tot[2]=4*128*128;
        j.src[3]=Wid1; j.dst_h[3]=(float*)BF(WT_ID1_H); j.dst_l[3]=(float*)BF(WT_ID1_L); j.K[3]=128; j.tot[3]=4*128*128;
        j.src[4]=Wid2; j.dst_h[4]=(float*)BF(WT_ID2_H); j.dst_l[4]=(float*)BF(WT_ID2_L); j.K[4]=128; j.tot[4]=4*128*128;
        j.src[5]=Wji;  j.dst_h[5]=(float*)BF(WT_JI_H);  j.dst_l[5]=(float*)BF(WT_JI_L);  j.K[5]=128; j.tot[5]=3*128*128;
        j.src[6]=Wkj;  j.dst_h[6]=(float*)BF(WT_KJ_H);  j.dst_l[6]=(float*)BF(WT_KJ_L);  j.K[6]=128; j.tot[6]=3*128*128;
        j.src[7]=Wres; j.dst_h[7]=(float*)BF(WT_RES_H); j.dst_l[7]=(float*)BF(WT_RES_L); j.K[7]=128; j.tot[7]=3*128*128;
        tsplit_all_kernel<<<dim3(64, 8), 256>>>(j);
    }

    // launch 3: embedding GEMM  <-- ncu capture target
    gemm_mma<<<GE, 256, SMEM_DYN>>>(nullptr, CATH, CATL,
                                    BF(WT_EMB_H), BF(WT_EMB_L), bemb,
                                    nullptr, nullptr,
                                    Worbf, idx_i, PAB(0), RBF,
                                    nullptr, XH, XL, EG, 384, 1);
    // launch 4: x0 gather
    x0_kernel<<<1024, 256>>>(Z, emb, X0);

    for (int i = 0; i < NB; i++) {
        size_t wo = (size_t)i * 128 * 128;
        gemm_mma<<<GE, 256, SMEM_DYN>>>(nullptr, XH, XL,
                                        BF(WT_KJ_H) + wo, BF(WT_KJ_L) + wo, bkj + (size_t)i*E,
                                        Wirbf + (size_t)i*NR*E, nullptr,
                                        nullptr, nullptr, nullptr, RBF,
                                        XKJ, nullptr, nullptr, EG, 128, 1);
        gemm_mma<<<GE, 256, SMEM_DYN>>>(nullptr, XH, XL,
                                        BF(WT_JI_H) + wo, BF(WT_JI_L) + wo, bji + (size_t)i*E,
                                        nullptr, nullptr, nullptr, nullptr, nullptr, nullptr,
                                        AGGR, nullptr, nullptr, EG, 128, 1);
        triplet_kernel<<<2048, 256>>>(XKJ, cosik, idx_kj, idx_ji,
                                      Wabf + (size_t)i*NABF*E, AGGR);
        gemm_mma<<<GE, 256, SMEM_DYN>>>(AGGR, nullptr, nullptr,
                                        BF(WT_RES_H) + wo, BF(WT_RES_L) + wo, bres + (size_t)i*E,
                                        nullptr, AGGR,
                                        Worbf + (size_t)(i+1)*NR*E, idx_i, PAB(i+1), RBF,
                                        nullptr, XH, XL, EG, 128, 1);
    }

    // output chains (blocks 0..3)
    for (int b = 0; b <= NB; b++) {
        size_t wo1 = (size_t)b * 128 * 128;
        gemm_mma<<<GA, 256, SMEM_DYN>>>(PAB(b), nullptr, nullptr,
                                        BF(WT_O1_H) + wo1, BF(WT_O1_L) + wo1, bo1 + (size_t)b*E,
                                        nullptr, nullptr, nullptr, nullptr, nullptr, nullptr,
                                        HAT, nullptr, nullptr, NA, 128, 1);
        gemm_mma<<<GA, 256, SMEM_DYN>>>(HAT, nullptr, nullptr,
                                        BF(WT_OUT_H) + wo1, BF(WT_OUT_L) + wo1, nullptr,
                                        nullptr, (b == 0) ? nullptr : ROUT,
                                        nullptr, nullptr, nullptr, nullptr,
                                        ROUT, nullptr, nullptr, NA, 128, 0);
    }

    // identity chain
    gemm_mma<<<GA, 256, SMEM_DYN>>>(X0, nullptr, nullptr, BF(WT_ID1_H), BF(WT_ID1_L), bid1,
                                    nullptr, nullptr, nullptr, nullptr, nullptr, nullptr,
                                    STMP, nullptr, nullptr, NA, 128, 1);
    gemm_mma<<<GA, 256, SMEM_DYN>>>(STMP, nullptr, nullptr, BF(WT_ID2_H), BF(WT_ID2_L), nullptr,
                                    nullptr, nullptr, nullptr, nullptr, nullptr, nullptr,
                                    RSING, nullptr, nullptr, NA, 128, 0);
    for (int b = 1; b <= NB; b++) {
        size_t wo1 = (size_t)b * 128 * 128;
        gemm_mma<<<GA, 256, SMEM_DYN>>>(RSING, nullptr, nullptr,
                                        BF(WT_ID1_H) + wo1, BF(WT_ID1_L) + wo1, bid1 + (size_t)b*E,
                                        nullptr, nullptr, nullptr, nullptr, nullptr, nullptr,
                                        STMP, nullptr, nullptr, NA, 128, 1);
        gemm_mma<<<GA, 256, SMEM_DYN>>>(STMP, nullptr, nullptr,
                                        BF(WT_ID2_H) + wo1, BF(WT_ID2_L) + wo1, nullptr,
                                        nullptr, RSING, nullptr, nullptr, nullptr, nullptr,
                                        RSING, nullptr, nullptr, NA, 128, 0);
    }

    // final
    cudaMemsetAsync(out, 0, (size_t)NM*E*sizeof(float));
    final_kernel<<<512, 256>>>(ROUT, RSING, bseg, cmp, csg, out);
}

// round 16
// speedup vs baseline: 1.4428x; 1.3012x over previous
#include <cuda_runtime.h>
#include <cuda_bf16.h>
#include <cstdint>
#include <cstddef>
#include <math.h>

// ---------------- problem constants ----------------
constexpr int EG  = 300000;   // edges
constexpr int TT  = 1000000;  // triplets
constexpr int NA  = 20000;    // atoms
constexpr int NM  = 1000;     // molecules
constexpr int E   = 128;      // embedding
constexpr int NR  = 6;
constexpr int NABF= 7;
constexpr int NB  = 3;

// ---------------- scratch layout (float granules) ----------------
constexpr size_t OFF_RBF  = 0;                                    // EG*6 f32
constexpr size_t OFF_CATH = OFF_RBF  + (size_t)EG*6;              // bf16[EG][384]
constexpr size_t OFF_CATL = OFF_CATH + (size_t)EG*192;
constexpr size_t OFF_XH   = OFF_CATL + (size_t)EG*192;            // bf16[EG][128]
constexpr size_t OFF_XL   = OFF_XH   + (size_t)EG*64;
constexpr size_t OFF_XKJ  = OFF_XL   + (size_t)EG*64;             // f32[EG][128]
constexpr size_t OFF_AGGR = OFF_XKJ  + (size_t)EG*128;
constexpr size_t OFF_PA   = OFF_AGGR + (size_t)EG*128;            // 4 x f32[NA][128]
constexpr size_t OFF_HAT  = OFF_PA   + (size_t)4*NA*128;
constexpr size_t OFF_ROUT = OFF_HAT  + (size_t)NA*128;
constexpr size_t OFF_RSING= OFF_ROUT + (size_t)NA*128;
constexpr size_t OFF_STMP = OFF_RSING+ (size_t)NA*128;
constexpr size_t OFF_X0   = OFF_STMP + (size_t)NA*128;
constexpr size_t OFF_WT   = OFF_X0   + (size_t)NA*128;
// inside WT (bf16 element offsets relative to BF(base))
constexpr size_t WT_EMB_H = 0;
constexpr size_t WT_EMB_L = 49152;
constexpr size_t WT_O1_H  = 98304;
constexpr size_t WT_O1_L  = 163840;
constexpr size_t WT_OUT_H = 229376;
constexpr size_t WT_OUT_L = 294912;
constexpr size_t WT_ID1_H = 360448;
constexpr size_t WT_ID1_L = 425984;
constexpr size_t WT_ID2_H = 491520;
constexpr size_t WT_ID2_L = 557056;
constexpr size_t WT_JI_H  = 622592;
constexpr size_t WT_JI_L  = 671744;
constexpr size_t WT_KJ_H  = 720896;
constexpr size_t WT_KJ_L  = 770048;
constexpr size_t WT_RES_H = 819200;
constexpr size_t WT_RES_L = 868352;
constexpr size_t WT_TOTAL = 917504;
constexpr size_t TOTAL_F  = OFF_WT + WT_TOTAL;

__device__ float g_buf[TOTAL_F];

// ---------------- helpers ----------------
__device__ __forceinline__ uint32_t smem_u32(const void* p) {
    uint32_t a;
    asm("{ .reg .u64 t; cvta.to.shared.u64 t, %1; cvt.u32.u64 %0, t; }" : "=r"(a) : "l"(p));
    return a;
}
__device__ __forceinline__ float silu_f(float x) { return x / (1.f + __expf(-x)); }

#define LDSM4(rr, addr) \
    asm volatile("ldmatrix.sync.aligned.m8n8.x4.shared.b16 {%0,%1,%2,%3}, [%4];" \
        : "=r"((rr)[0]), "=r"((rr)[1]), "=r"((rr)[2]), "=r"((rr)[3]) : "r"(addr))

#define MMA_BF16(d, a, b0, b1) \
    asm volatile("mma.sync.aligned.m16n8k16.row.col.f32.bf16.bf16.f32 " \
        "{%0,%1,%2,%3},{%4,%5,%6,%7},{%8,%9},{%0,%1,%2,%3};" \
        : "+f"((d)[0]), "+f"((d)[1]), "+f"((d)[2]), "+f"((d)[3]) \
        : "r"((a)[0]), "r"((a)[1]), "r"((a)[2]), "r"((a)[3]), "r"(b0), "r"(b1))

#define CP_ASYNC16(dst, src) \
    asm volatile("cp.async.cg.shared.global [%0], [%1], 16;" :: "r"(dst), "l"(src) : "memory")
#define CP_COMMIT() asm volatile("cp.async.commit_group;" ::: "memory")
#define CP_WAIT0()  asm volatile("cp.async.wait_group 0;" ::: "memory")

#define RED4(ptr, a, b, c, dd) \
    asm volatile("red.global.add.v4.f32 [%0], {%1,%2,%3,%4};" \
        :: "l"(ptr), "f"(a), "f"(b), "f"(c), "f"(dd) : "memory")
#define RED2(ptr, a, b) \
    asm volatile("red.global.add.v2.f32 [%0], {%1,%2};" \
        :: "l"(ptr), "f"(a), "f"(b) : "memory")

__device__ __forceinline__ uint32_t pack_bf16_hi(float a, float b, float& la, float& lb) {
    __nv_bfloat162 h = __floats2bfloat162_rn(a, b);
    la = a - __bfloat162float(h.x);
    lb = b - __bfloat162float(h.y);
    return *(uint32_t*)&h;
}
__device__ __forceinline__ uint32_t pack_bf16(float a, float b) {
    __nv_bfloat162 h = __floats2bfloat162_rn(a, b);
    return *(uint32_t*)&h;
}

// ---------------- smem layout (bytes after 1024-align): single stage ----------------
constexpr int TILE  = 16384;
constexpr int SM_AH   = 0;
constexpr int SM_AL   = TILE;
constexpr int SM_BH   = 2 * TILE;
constexpr int SM_BL   = 3 * TILE;          // ends 65536
constexpr int SM_WMUL = 65536;
constexpr int SM_WSC  = 68608;
constexpr int SM_RBF6 = 71680;
constexpr int SM_BIAS = 74752;
constexpr int SM_END  = 75264;
constexpr int SMEM_DYN = SM_END + 1024 + 128;   // ~76.4 KB -> 2 CTAs/SM fit smem

// ---------------- launch 0: rbf + zero PA buffers ----------------
__global__ void rbf_kernel(const float* __restrict__ R,
                           const int* __restrict__ idx_i,
                           const int* __restrict__ idx_j,
                           float* __restrict__ rbf,
                           float* __restrict__ pa4)
{
    const float PI_F = 3.14159265358979323846f;
    const float c = sqrtf(2.f / 5.f);
    int gtid = blockIdx.x * blockDim.x + threadIdx.x;
    int gstr = gridDim.x * blockDim.x;
    size_t pn = (size_t)4*NA*128/4;
    float4 z = make_float4(0.f,0.f,0.f,0.f);
    for (size_t i = gtid; i < pn; i += gstr) ((float4*)pa4)[i] = z;
    for (int e = gtid; e < EG; e += gstr) {
        int i = idx_i[e], j = idx_j[e];
        float dx = R[3*i+0] - R[3*j+0];
        float dy = R[3*i+1] - R[3*j+1];
        float dz = R[3*i+2] - R[3*j+2];
        float d = sqrtf(dx*dx + dy*dy + dz*dz);
        d = fmaxf(d, 1e-2f);
        float inv = 1.f / d;
        float arg = d * (PI_F / 5.f);
        float s1, c1;
        __sincosf(arg, &s1, &c1);
        float tc = 2.f * c1;
        float sm1 = 0.f, s = s1;
        #pragma unroll
        for (int r = 0; r < NR; r++) {
            rbf[(size_t)e*NR + r] = c * s * inv;
            float nx = tc * s - sm1;
            sm1 = s; s = nx;
        }
    }
}

__global__ void x0_kernel(const int* __restrict__ Z,
                          const float* __restrict__ emb,
                          float* __restrict__ x0)
{
    size_t total = (size_t)NA * E;
    for (size_t idx = blockIdx.x * (size_t)blockDim.x + threadIdx.x; idx < total;
         idx += (size_t)gridDim.x * blockDim.x) {
        int a = (int)(idx >> 7);
        int c = (int)(idx & 127);
        x0[idx] = emb[(size_t)Z[a]*E + c];
    }
}

// coalesced buildcat
__global__ __launch_bounds__(128) void buildcat_kernel(
    const int* __restrict__ Z,
    const int* __restrict__ idx_i,
    const int* __restrict__ idx_j,
    const float* __restrict__ emb,
    const float* __restrict__ Wrbf,
    const float* __restrict__ rbf,
    __nv_bfloat16* __restrict__ ch_,
    __nv_bfloat16* __restrict__ cl_)
{
    __shared__ float ws[NR*E];
    for (int k = threadIdx.x; k < NR*E; k += 128) ws[k] = Wrbf[k];
    __syncthreads();
    int half = threadIdx.x >> 6;
    int c2 = threadIdx.x & 63;
    int c0 = c2 * 2;
    for (int eb = blockIdx.x * 2; eb < EG; eb += gridDim.x * 2) {
        int e = eb + half;
        if (e >= EG) continue;
        int ai = idx_i[e], aj = idx_j[e];
        float r0 = rbf[(size_t)e*NR+0], r1 = rbf[(size_t)e*NR+1], r2 = rbf[(size_t)e*NR+2];
        float r3 = rbf[(size_t)e*NR+3], r4 = rbf[(size_t)e*NR+4], r5 = rbf[(size_t)e*NR+5];
        float s0 = r0*ws[c0]     + r1*ws[E+c0]     + r2*ws[2*E+c0]
                 + r3*ws[3*E+c0] + r4*ws[4*E+c0]   + r5*ws[5*E+c0];
        float s1 = r0*ws[c0+1]   + r1*ws[E+c0+1]   + r2*ws[2*E+c0+1]
                 + r3*ws[3*E+c0+1] + r4*ws[4*E+c0+1] + r5*ws[5*E+c0+1];
        s0 = silu_f(s0); s1 = silu_f(s1);
        float2 vi = *(const float2*)&emb[(size_t)Z[ai]*E + c0];
        float2 vj = *(const float2*)&emb[(size_t)Z[aj]*E + c0];
        size_t base = (size_t)e * 384;
        float l0, l1;
        uint32_t h;
        h = pack_bf16_hi(vi.x, vi.y, l0, l1);
        *(uint32_t*)&ch_[base + c0] = h;
        *(uint32_t*)&cl_[base + c0] = pack_bf16(l0, l1);
        h = pack_bf16_hi(vj.x, vj.y, l0, l1);
        *(uint32_t*)&ch_[base + 128 + c0] = h;
        *(uint32_t*)&cl_[base + 128 + c0] = pack_bf16(l0, l1);
        h = pack_bf16_hi(s0, s1, l0, l1);
        *(uint32_t*)&ch_[base + 256 + c0] = h;
        *(uint32_t*)&cl_[base + 256 + c0] = pack_bf16(l0, l1);
    }
}

// ---- batched transpose+split ----
struct TsplitJobs {
    const float* src[8];
    float* dst_h[8];
    float* dst_l[8];
    int K[8];
    int tot[8];
};
__global__ void tsplit_all_kernel(TsplitJobs jobs)
{
    int j = blockIdx.y;
    const float* s = jobs.src[j];
    __nv_bfloat16* h = (__nv_bfloat16*)jobs.dst_h[j];
    __nv_bfloat16* l = (__nv_bfloat16*)jobs.dst_l[j];
    int K = jobs.K[j];
    int tot = jobs.tot[j];
    int per = K * 128;
    for (int idx = blockIdx.x * blockDim.x + threadIdx.x; idx < tot;
         idx += gridDim.x * blockDim.x) {
        int b = idx / per;
        int rem = idx - b * per;
        int k = rem >> 7, n = rem & 127;
        float v = s[idx];
        __nv_bfloat16 hi = __float2bfloat16(v);
        float lo = v - __bfloat162float(hi);
        h[(size_t)b*per + (size_t)n*K + k] = hi;
        l[(size_t)b*per + (size_t)n*K + k] = __float2bfloat16(lo);
    }
}

// ---------------- mma.sync bf16x3 GEMM, single-buffer, 2 CTAs/SM ----------------
__global__ __launch_bounds__(256, 2) void gemm_mma(
    const float* __restrict__ A,
    const __nv_bfloat16* __restrict__ A16h,
    const __nv_bfloat16* __restrict__ A16l,
    const __nv_bfloat16* __restrict__ Bh,
    const __nv_bfloat16* __restrict__ Bl,
    const float* __restrict__ bias,
    const float* __restrict__ mulW,
    const float* __restrict__ addp,
    const float* __restrict__ scW,
    const int* __restrict__ sc_idx, float* __restrict__ sc_out,
    const float* __restrict__ rbf,
    float* __restrict__ C,
    __nv_bfloat16* __restrict__ C16h,
    __nv_bfloat16* __restrict__ C16l,
    int M, int K, int act)
{
    extern __shared__ char smraw[];
    char* sm = (char*)(((uintptr_t)smraw + 1023) & ~(uintptr_t)1023);
    uint32_t smb = smem_u32(sm);
    float* wmul_s = (float*)(sm + SM_WMUL);
    float* wsc_s  = (float*)(sm + SM_WSC);
    float* rbf6   = (float*)(sm + SM_RBF6);
    float* bias_s = (float*)(sm + SM_BIAS);

    int tid = threadIdx.x;
    int lane = tid & 31;
    int wid = tid >> 5;
    int bm = blockIdx.x * 128;
    int need_rbf = (mulW != nullptr) || (scW != nullptr);

    for (int k = tid; k < NR*E; k += 256) {
        if (mulW) wmul_s[k] = mulW[k];
        if (scW)  wsc_s[k]  = scW[k];
    }
    for (int k = tid; k < E; k += 256) bias_s[k] = bias ? bias[k] : 0.f;
    if (need_rbf && tid < 128) {
        int g = bm + tid; if (g >= M) g = M - 1;
        #pragma unroll
        for (int q = 0; q < NR; q++) rbf6[tid*NR + q] = rbf[(size_t)g*NR + q];
    }
    __syncthreads();

    int wm = (wid & 3) * 32;
    int wn = (wid >> 2) * 64;
    int lq = lane >> 2;
    int lr4 = lane & 3;
    int r  = lane & 7;
    int mi = lane >> 3;
    uint32_t AHb = smb + SM_AH + (uint32_t)((wm + (mi&1)*8 + r) * 128);
    uint32_t ALb = AHb + TILE;
    int a_chsel = mi >> 1;
    uint32_t BHb = smb + SM_BH + (uint32_t)((wn + ((mi>>1)&1)*8 + r) * 128);
    uint32_t BLb = BHb + TILE;
    int b_chsel = mi & 1;

    float acc[2][8][4];
    #pragma unroll
    for (int a0 = 0; a0 < 2; a0++)
        #pragma unroll
        for (int b0 = 0; b0 < 8; b0++)
            #pragma unroll
            for (int c0 = 0; c0 < 4; c0++) acc[a0][b0][c0] = 0.f;

    int nch = K >> 6;
    for (int c = 0; c < nch; c++) {
        int kc = c << 6;

        #pragma unroll
        for (int u = 0; u < 8; u++) {
            int f = u*256 + tid;
            int which = f >> 10;
            int g2 = f & 1023;
            int n = g2 >> 3, ch = g2 & 7;
            const __nv_bfloat16* src = (which ? Bl : Bh) + (size_t)n*K + kc + ch*8;
            uint32_t dst = smb + (which ? SM_BL : SM_BH)
                         + (uint32_t)(n*128 + ((ch ^ (n & 7)) << 4));
            CP_ASYNC16(dst, src);
        }
        if (A16h) {
            #pragma unroll
            for (int u = 0; u < 8; u++) {
                int f = u*256 + tid;
                int which = f >> 10;
                int g2 = f & 1023;
                int rr = g2 >> 3, ch = g2 & 7;
                int g = bm + rr; if (g >= M) g = M - 1;
                const __nv_bfloat16* src = (which ? A16l : A16h) + (size_t)g*K + kc + ch*8;
                uint32_t dst = smb + (which ? SM_AL : SM_AH)
                             + (uint32_t)(rr*128 + ((ch ^ (rr & 7)) << 4));
                CP_ASYNC16(dst, src);
            }
            CP_COMMIT();
            CP_WAIT0();
        } else {
            CP_COMMIT();
            #pragma unroll
            for (int u = 0; u < 4; u++) {
                int f = u*256 + tid;
                int rr = f >> 3, ch = f & 7;
                int g = bm + rr;
                int k = kc + ch*8;
                float v[8];
                if (g < M) {
                    float4 p0 = *(const float4*)&A[(size_t)g*K + k];
                    float4 p1 = *(const float4*)&A[(size_t)g*K + k + 4];
                    v[0]=p0.x; v[1]=p0.y; v[2]=p0.z; v[3]=p0.w;
                    v[4]=p1.x; v[5]=p1.y; v[6]=p1.z; v[7]=p1.w;
                } else {
                    #pragma unroll
                    for (int e2 = 0; e2 < 8; e2++) v[e2] = 0.f;
                }
                uint4 hb, lb;
                float l0, l1;
                hb.x = pack_bf16_hi(v[0], v[1], l0, l1); lb.x = pack_bf16(l0, l1);
                hb.y = pack_bf16_hi(v[2], v[3], l0, l1); lb.y = pack_bf16(l0, l1);
                hb.z = pack_bf16_hi(v[4], v[5], l0, l1); lb.z = pack_bf16(l0, l1);
                hb.w = pack_bf16_hi(v[6], v[7], l0, l1); lb.w = pack_bf16(l0, l1);
                uint32_t sw = (uint32_t)(rr*128 + ((ch ^ (rr & 7)) << 4));
                *(uint4*)(sm + SM_AH + sw) = hb;
                *(uint4*)(sm + SM_AL + sw) = lb;
            }
            CP_WAIT0();
        }
        __syncthreads();

        #pragma unroll
        for (int ks = 0; ks < 4; ks++) {
            uint32_t aswz = (uint32_t)(((2*ks + a_chsel) ^ r) << 4);
            uint32_t bswz = (uint32_t)(((2*ks + b_chsel) ^ r) << 4);
            uint32_t ah[2][4], al[2][4];
            LDSM4(ah[0], AHb + aswz);
            LDSM4(ah[1], AHb + 2048 + aswz);
            LDSM4(al[0], ALb + aswz);
            LDSM4(al[1], ALb + 2048 + aswz);
            #pragma unroll
            for (int p = 0; p < 4; p++) {
                uint32_t bh[4], bl[4];
                LDSM4(bh, BHb + (uint32_t)(p*2048) + bswz);
                LDSM4(bl, BLb + (uint32_t)(p*2048) + bswz);
                #pragma unroll
                for (int mt = 0; mt < 2; mt++) {
                    MMA_BF16(acc[mt][2*p+0], ah[mt], bh[0], bh[1]);
                    MMA_BF16(acc[mt][2*p+0], ah[mt], bl[0], bl[1]);
                    MMA_BF16(acc[mt][2*p+0], al[mt], bh[0], bh[1]);
                    MMA_BF16(acc[mt][2*p+1], ah[mt], bh[2], bh[3]);
                    MMA_BF16(acc[mt][2*p+1], ah[mt], bl[2], bl[3]);
                    MMA_BF16(acc[mt][2*p+1], al[mt], bh[2], bh[3]);
                }
            }
        }
        __syncthreads();
    }

    // ---- epilogue (R9-exact) ----
    #pragma unroll
    for (int mt = 0; mt < 2; mt++) {
        int lrbase = wm + mt*16 + lq;
        #pragma unroll
        for (int h = 0; h < 2; h++) {
            int lrow = lrbase + h*8;
            int row = bm + lrow;
            if (row >= M) continue;
            int asc = scW ? sc_idx[row] : 0;
            #pragma unroll
            for (int nt = 0; nt < 8; nt++) {
                int col = wn + nt*8 + lr4*2;
                float v0 = acc[mt][nt][2*h+0] + bias_s[col];
                float v1 = acc[mt][nt][2*h+1] + bias_s[col+1];
                if (act) { v0 = silu_f(v0); v1 = silu_f(v1); }
                if (mulW) {
                    float d0 = 0.f, d1 = 0.f;
                    #pragma unroll
                    for (int q = 0; q < NR; q++) {
                        float rq = rbf6[lrow*NR + q];
                        d0 += rq * wmul_s[q*E + col];
                        d1 += rq * wmul_s[q*E + col + 1];
                    }
                    v0 *= d0; v1 *= d1;
                }
                if (addp) {
                    float2 av = *(const float2*)&addp[(size_t)row*128 + col];
                    v0 += av.x; v1 += av.y;
                }
                if (C) *(float2*)&C[(size_t)row*128 + col] = make_float2(v0, v1);
                if (C16h) {
                    float l0, l1;
                    uint32_t hb = pack_bf16_hi(v0, v1, l0, l1);
                    uint32_t lb = pack_bf16(l0, l1);
                    *(uint32_t*)&C16h[(size_t)row*128 + col] = hb;
                    *(uint32_t*)&C16l[(size_t)row*128 + col] = lb;
                }
                if (scW) {
                    float g0 = 0.f, g1 = 0.f;
                    #pragma unroll
                    for (int q = 0; q < NR; q++) {
                        float rq = rbf6[lrow*NR + q];
                        g0 += rq * wsc_s[q*E + col];
                        g1 += rq * wsc_s[q*E + col + 1];
                    }
                    RED2(&sc_out[(size_t)asc*128 + col], g0*v0, g1*v1);
                }
            }
        }
    }
}

// ---------------- triplet messages + atomic scatter (unroll x2) ----------------
__global__ __launch_bounds__(256) void triplet_kernel(
    const float* __restrict__ xkj,
    const float* __restrict__ cosik,
    const int* __restrict__ idx_kj,
    const int* __restrict__ idx_ji,
    const float* __restrict__ Wabf,       // [7,128]
    float* __restrict__ aggr)
{
    __shared__ float ws[NABF*E];
    for (int k = threadIdx.x; k < NABF*E; k += 256) ws[k] = Wabf[k];
    __syncthreads();
    int lane = threadIdx.x & 31;
    int warp = (blockIdx.x * 256 + threadIdx.x) >> 5;
    int nwarps = (gridDim.x * 256) >> 5;
    int c = lane << 2;
    for (int t = warp * 2; t < TT; t += nwarps * 2) {
        int ekj0 = idx_kj[t],   eji0 = idx_ji[t];
        int ekj1 = idx_kj[t+1], eji1 = idx_ji[t+1];
        float xa = fminf(1.f, fmaxf(-1.f, cosik[t]));
        float xb = fminf(1.f, fmaxf(-1.f, cosik[t+1]));
        float4 xv0 = *(const float4*)&xkj[(size_t)ekj0*128 + c];
        float4 xv1 = *(const float4*)&xkj[(size_t)ekj1*128 + c];
        float a1=xa, a2=2.f*xa*a1-1.f, a3=2.f*xa*a2-a1, a4=2.f*xa*a3-a2,
              a5=2.f*xa*a4-a3, a6=2.f*xa*a5-a4;
        float b1=xb, b2=2.f*xb*b1-1.f, b3=2.f*xb*b2-b1, b4=2.f*xb*b3-b2,
              b5=2.f*xb*b4-b3, b6=2.f*xb*b5-b4;
        float m0[4], m1[4];
        #pragma unroll
        for (int j = 0; j < 4; j++) {
            int cc = c + j;
            float w0=ws[cc], w1=ws[E+cc], w2=ws[2*E+cc], w3=ws[3*E+cc],
                  w4=ws[4*E+cc], w5=ws[5*E+cc], w6=ws[6*E+cc];
            m0[j] = w0 + a1*w1 + a2*w2 + a3*w3 + a4*w4 + a5*w5 + a6*w6;
            m1[j] = w0 + b1*w1 + b2*w2 + b3*w3 + b4*w4 + b5*w5 + b6*w6;
        }
        RED4(&aggr[(size_t)eji0*128 + c], xv0.x*m0[0], xv0.y*m0[1], xv0.z*m0[2], xv0.w*m0[3]);
        RED4(&aggr[(size_t)eji1*128 + c], xv1.x*m1[0], xv1.y*m1[1], xv1.z*m1[2], xv1.w*m1[3]);
    }
}

// ---------------- final molecule reduction ----------------
__global__ void final_kernel(const float* __restrict__ ro,
                             const float* __restrict__ rs,
                             const int* __restrict__ bseg,
                             const float* __restrict__ cmp_p,
                             const float* __restrict__ csg_p,
                             float* __restrict__ out)
{
    float cmp = cmp_p[0], csg = csg_p[0];
    size_t total = (size_t)NA * 32;
    for (size_t idx = blockIdx.x * (size_t)blockDim.x + threadIdx.x; idx < total;
         idx += (size_t)gridDim.x * blockDim.x) {
        int a = (int)(idx >> 5);
        int c = (int)(idx & 31) << 2;
        int m = bseg[a];
        float4 o = *(const float4*)&ro[(size_t)a*128 + c];
        float4 s = *(const float4*)&rs[(size_t)a*128 + c];
        RED4(&out[(size_t)m*128 + c],
             cmp*o.x + csg*s.x, cmp*o.y + csg*s.y,
             cmp*o.z + csg*s.z, cmp*o.w + csg*s.w);
    }
}

// ---------------- host orchestration (serial stream 0) ----------------
extern "C" void kernel_launch(void* const* d_in, const int* in_sizes, int n_in,
                              void* d_out, int out_size)
{
    const int*   Z      = (const int*)  d_in[0];
    const float* R      = (const float*)d_in[1];
    const int*   bseg   = (const int*)  d_in[2];
    const int*   idx_i  = (const int*)  d_in[3];
    const int*   idx_j  = (const int*)  d_in[4];
    const int*   idx_kj = (const int*)  d_in[5];
    const int*   idx_ji = (const int*)  d_in[6];
    const float* cosik  = (const float*)d_in[7];
    const float* emb    = (const float*)d_in[8];
    const float* Wrbf   = (const float*)d_in[9];
    const float* Wemb   = (const float*)d_in[10];
    const float* bemb   = (const float*)d_in[11];
    const float* Worbf  = (const float*)d_in[12];
    const float* Wo1    = (const float*)d_in[13];
    const float* bo1    = (const float*)d_in[14];
    const float* Wout   = (const float*)d_in[15];
    const float* Wid1   = (const float*)d_in[16];
    const float* bid1   = (const float*)d_in[17];
    const float* Wid2   = (const float*)d_in[18];
    const float* Wji    = (const float*)d_in[19];
    const float* bji    = (const float*)d_in[20];
    const float* Wkj    = (const float*)d_in[21];
    const float* bkj    = (const float*)d_in[22];
    const float* Wirbf  = (const float*)d_in[23];
    const float* Wabf   = (const float*)d_in[24];
    const float* Wres   = (const float*)d_in[25];
    const float* bres   = (const float*)d_in[26];
    const float* cmp    = (const float*)d_in[27];
    const float* csg    = (const float*)d_in[28];
    float* out = (float*)d_out;

    cudaFuncSetAttribute(gemm_mma, cudaFuncAttributeMaxDynamicSharedMemorySize, SMEM_DYN);

    float* buf = nullptr;
    cudaGetSymbolAddress((void**)&buf, g_buf);
    float* RBF   = buf + OFF_RBF;
    __nv_bfloat16* CATH = (__nv_bfloat16*)(buf + OFF_CATH);
    __nv_bfloat16* CATL = (__nv_bfloat16*)(buf + OFF_CATL);
    __nv_bfloat16* XH   = (__nv_bfloat16*)(buf + OFF_XH);
    __nv_bfloat16* XL   = (__nv_bfloat16*)(buf + OFF_XL);
    float* XKJ   = buf + OFF_XKJ;
    float* AGGR  = buf + OFF_AGGR;
    float* PA    = buf + OFF_PA;
    float* HAT   = buf + OFF_HAT;
    float* ROUT  = buf + OFF_ROUT;
    float* RSING = buf + OFF_RSING;
    float* STMP  = buf + OFF_STMP;
    float* X0    = buf + OFF_X0;
    float* WT    = buf + OFF_WT;

    #define BF(off) ((__nv_bfloat16*)(WT + (off)))
    #define PAB(b)  (PA + (size_t)(b)*NA*128)

    const int GE = (EG + 127) / 128;
    const int GA = (NA + 127) / 128;

    // launch 0: rbf + zero 4 PA buffers
    rbf_kernel<<<1024, 256>>>(R, idx_i, idx_j, RBF, PA);
    // launch 1: buildcat
    buildcat_kernel<<<4096, 128>>>(Z, idx_i, idx_j, emb, Wrbf, RBF, CATH, CATL);
    // launch 2: all weight splits
    {
        TsplitJobs j;
        j.src[0]=Wemb; j.dst_h[0]=(float*)BF(WT_EMB_H); j.dst_l[0]=(float*)BF(WT_EMB_L); j.K[0]=384; j.tot[0]=384*128;
        j.src[1]=Wo1;  j.dst_h[1]=(float*)BF(WT_O1_H);  j.dst_l[1]=(float*)BF(WT_O1_L);  j.K[1]=128; j.tot[1]=4*128*128;
        j.src[2]=Wout; j.dst_h[2]=(float*)BF(WT_OUT_H); j.dst_l[2]=(float*)BF(WT_OUT_L); j.K[2]=128; j.tot[2]=4*128*128;
        j.src[3]=Wid1; j.dst_h[3]=(float*)BF(WT_ID1_H); j.dst_l[3]=(float*)BF(WT_ID1_L); j.K[3]=128; j.tot[3]=4*128*128;
        j.src[4]=Wid2; j.dst_h[4]=(float*)BF(WT_ID2_H); j.dst_l[4]=(float*)BF(WT_ID2_L); j.K[4]=128; j.tot[4]=4*128*128;
        j.src[5]=Wji;  j.dst_h[5]=(float*)BF(WT_JI_H);  j.dst_l[5]=(float*)BF(WT_JI_L);  j.K[5]=128; j.tot[5]=3*128*128;
        j.src[6]=Wkj;  j.dst_h[6]=(float*)BF(WT_KJ_H);  j.dst_l[6]=(float*)BF(WT_KJ_L);  j.K[6]=128; j.tot[6]=3*128*128;
        j.src[7]=Wres; j.dst_h[7]=(float*)BF(WT_RES_H); j.dst_l[7]=(float*)BF(WT_RES_L); j.K[7]=128; j.tot[7]=3*128*128;
        tsplit_all_kernel<<<dim3(64, 8), 256>>>(j);
    }

    // launch 3: embedding GEMM  <-- ncu capture target
    gemm_mma<<<GE, 256, SMEM_DYN>>>(nullptr, CATH, CATL,
                                    BF(WT_EMB_H), BF(WT_EMB_L), bemb,
                                    nullptr, nullptr,
                                    Worbf, idx_i, PAB(0), RBF,
                                    nullptr, XH, XL, EG, 384, 1);
    // launch 4: x0 gather
    x0_kernel<<<1024, 256>>>(Z, emb, X0);

    for (int i = 0; i < NB; i++) {
        size_t wo = (size_t)i * 128 * 128;
        gemm_mma<<<GE, 256, SMEM_DYN>>>(nullptr, XH, XL,
                                        BF(WT_KJ_H) + wo, BF(WT_KJ_L) + wo, bkj + (size_t)i*E,
                                        Wirbf + (size_t)i*NR*E, nullptr,
                                        nullptr, nullptr, nullptr, RBF,
                                        XKJ, nullptr, nullptr, EG, 128, 1);
        gemm_mma<<<GE, 256, SMEM_DYN>>>(nullptr, XH, XL,
                                        BF(WT_JI_H) + wo, BF(WT_JI_L) + wo, bji + (size_t)i*E,
                                        nullptr, nullptr, nullptr, nullptr, nullptr, nullptr,
                                        AGGR, nullptr, nullptr, EG, 128, 1);
        triplet_kernel<<<2048, 256>>>(XKJ, cosik, idx_kj, idx_ji,
                                      Wabf + (size_t)i*NABF*E, AGGR);
        gemm_mma<<<GE, 256, SMEM_DYN>>>(AGGR, nullptr, nullptr,
                                        BF(WT_RES_H) + wo, BF(WT_RES_L) + wo, bres + (size_t)i*E,
                                        nullptr, AGGR,
                                        Worbf + (size_t)(i+1)*NR*E, idx_i, PAB(i+1), RBF,
                                        nullptr, XH, XL, EG, 128, 1);
    }

    // output chains (blocks 0..3)
    for (int b = 0; b <= NB; b++) {
        size_t wo1 = (size_t)b * 128 * 128;
        gemm_mma<<<GA, 256, SMEM_DYN>>>(PAB(b), nullptr, nullptr,
                                        BF(WT_O1_H) + wo1, BF(WT_O1_L) + wo1, bo1 + (size_t)b*E,
                                        nullptr, nullptr, nullptr, nullptr, nullptr, nullptr,
                                        HAT, nullptr, nullptr, NA, 128, 1);
        gemm_mma<<<GA, 256, SMEM_DYN>>>(HAT, nullptr, nullptr,
                                        BF(WT_OUT_H) + wo1, BF(WT_OUT_L) + wo1, nullptr,
                                        nullptr, (b == 0) ? nullptr : ROUT,
                                        nullptr, nullptr, nullptr, nullptr,
                                        ROUT, nullptr, nullptr, NA, 128, 0);
    }

    // identity chain
    gemm_mma<<<GA, 256, SMEM_DYN>>>(X0, nullptr, nullptr, BF(WT_ID1_H), BF(WT_ID1_L), bid1,
                                    nullptr, nullptr, nullptr, nullptr, nullptr, nullptr,
                                    STMP, nullptr, nullptr, NA, 128, 1);
    gemm_mma<<<GA, 256, SMEM_DYN>>>(STMP, nullptr, nullptr, BF(WT_ID2_H), BF(WT_ID2_L), nullptr,
                                    nullptr, nullptr, nullptr, nullptr, nullptr, nullptr,
                                    RSING, nullptr, nullptr, NA, 128, 0);
    for (int b = 1; b <= NB; b++) {
        size_t wo1 = (size_t)b * 128 * 128;
        gemm_mma<<<GA, 256, SMEM_DYN>>>(RSING, nullptr, nullptr,
                                        BF(WT_ID1_H) + wo1, BF(WT_ID1_L) + wo1, bid1 + (size_t)b*E,
                                        nullptr, nullptr, nullptr, nullptr, nullptr, nullptr,
                                        STMP, nullptr, nullptr, NA, 128, 1);
        gemm_mma<<<GA, 256, SMEM_DYN>>>(STMP, nullptr, nullptr,
                                        BF(WT_ID2_H) + wo1, BF(WT_ID2_L) + wo1, nullptr,
                                        nullptr, RSING, nullptr, nullptr, nullptr, nullptr,
                                        RSING, nullptr, nullptr, NA, 128, 0);
    }

    // final
    cudaMemsetAsync(out, 0, (size_t)NM*E*sizeof(float));
    final_kernel<<<512, 256>>>(ROUT, RSING, bseg, cmp, csg, out);
}

// round 17
// speedup vs baseline: 1.4564x; 1.0094x over previous
#include <cuda_runtime.h>
#include <cuda_bf16.h>
#include <cuda_fp16.h>
#include <cstdint>
#include <cstddef>
#include <math.h>

// ---------------- problem constants ----------------
constexpr int EG  = 300000;   // edges
constexpr int TT  = 1000000;  // triplets
constexpr int NA  = 20000;    // atoms
constexpr int NM  = 1000;     // molecules
constexpr int E   = 128;      // embedding
constexpr int NR  = 6;
constexpr int NABF= 7;
constexpr int NB  = 3;

// ---------------- scratch layout (float granules) ----------------
constexpr size_t OFF_RBF  = 0;                                    // EG*6 f32
constexpr size_t OFF_CATH = OFF_RBF  + (size_t)EG*6;              // bf16[EG][384]
constexpr size_t OFF_CATL = OFF_CATH + (size_t)EG*192;
constexpr size_t OFF_XH   = OFF_CATL + (size_t)EG*192;            // bf16[EG][128]
constexpr size_t OFF_XL   = OFF_XH   + (size_t)EG*64;
constexpr size_t OFF_XKJ  = OFF_XL   + (size_t)EG*64;             // fp16[EG][128] (half slot)
constexpr size_t OFF_AGGR = OFF_XKJ  + (size_t)EG*128;
constexpr size_t OFF_PA   = OFF_AGGR + (size_t)EG*128;            // 4 x f32[NA][128]
constexpr size_t OFF_HAT  = OFF_PA   + (size_t)4*NA*128;
constexpr size_t OFF_ROUT = OFF_HAT  + (size_t)NA*128;
constexpr size_t OFF_RSING= OFF_ROUT + (size_t)NA*128;
constexpr size_t OFF_STMP = OFF_RSING+ (size_t)NA*128;
constexpr size_t OFF_X0   = OFF_STMP + (size_t)NA*128;
constexpr size_t OFF_WT   = OFF_X0   + (size_t)NA*128;
// inside WT (bf16 element offsets relative to BF(base))
constexpr size_t WT_EMB_H = 0;
constexpr size_t WT_EMB_L = 49152;
constexpr size_t WT_O1_H  = 98304;
constexpr size_t WT_O1_L  = 163840;
constexpr size_t WT_OUT_H = 229376;
constexpr size_t WT_OUT_L = 294912;
constexpr size_t WT_ID1_H = 360448;
constexpr size_t WT_ID1_L = 425984;
constexpr size_t WT_ID2_H = 491520;
constexpr size_t WT_ID2_L = 557056;
constexpr size_t WT_JI_H  = 622592;
constexpr size_t WT_JI_L  = 671744;
constexpr size_t WT_KJ_H  = 720896;
constexpr size_t WT_KJ_L  = 770048;
constexpr size_t WT_RES_H = 819200;
constexpr size_t WT_RES_L = 868352;
constexpr size_t WT_TOTAL = 917504;
constexpr size_t TOTAL_F  = OFF_WT + WT_TOTAL;

__device__ float g_buf[TOTAL_F];

// ---------------- helpers ----------------
__device__ __forceinline__ uint32_t smem_u32(const void* p) {
    uint32_t a;
    asm("{ .reg .u64 t; cvta.to.shared.u64 t, %1; cvt.u32.u64 %0, t; }" : "=r"(a) : "l"(p));
    return a;
}
__device__ __forceinline__ float silu_f(float x) { return x / (1.f + __expf(-x)); }

#define LDSM4(rr, addr) \
    asm volatile("ldmatrix.sync.aligned.m8n8.x4.shared.b16 {%0,%1,%2,%3}, [%4];" \
        : "=r"((rr)[0]), "=r"((rr)[1]), "=r"((rr)[2]), "=r"((rr)[3]) : "r"(addr))

#define MMA_BF16(d, a, b0, b1) \
    asm volatile("mma.sync.aligned.m16n8k16.row.col.f32.bf16.bf16.f32 " \
        "{%0,%1,%2,%3},{%4,%5,%6,%7},{%8,%9},{%0,%1,%2,%3};" \
        : "+f"((d)[0]), "+f"((d)[1]), "+f"((d)[2]), "+f"((d)[3]) \
        : "r"((a)[0]), "r"((a)[1]), "r"((a)[2]), "r"((a)[3]), "r"(b0), "r"(b1))

#define CP_ASYNC16(dst, src) \
    asm volatile("cp.async.cg.shared.global [%0], [%1], 16;" :: "r"(dst), "l"(src) : "memory")
#define CP_COMMIT() asm volatile("cp.async.commit_group;" ::: "memory")
#define CP_WAIT0()  asm volatile("cp.async.wait_group 0;" ::: "memory")

#define RED4(ptr, a, b, c, dd) \
    asm volatile("red.global.add.v4.f32 [%0], {%1,%2,%3,%4};" \
        :: "l"(ptr), "f"(a), "f"(b), "f"(c), "f"(dd) : "memory")
#define RED2(ptr, a, b) \
    asm volatile("red.global.add.v2.f32 [%0], {%1,%2};" \
        :: "l"(ptr), "f"(a), "f"(b) : "memory")

__device__ __forceinline__ uint32_t pack_bf16_hi(float a, float b, float& la, float& lb) {
    __nv_bfloat162 h = __floats2bfloat162_rn(a, b);
    la = a - __bfloat162float(h.x);
    lb = b - __bfloat162float(h.y);
    return *(uint32_t*)&h;
}
__device__ __forceinline__ uint32_t pack_bf16(float a, float b) {
    __nv_bfloat162 h = __floats2bfloat162_rn(a, b);
    return *(uint32_t*)&h;
}

// ---------------- smem layout (bytes after 1024-align): single stage ----------------
constexpr int TILE  = 16384;
constexpr int SM_AH   = 0;
constexpr int SM_AL   = TILE;
constexpr int SM_BH   = 2 * TILE;
constexpr int SM_BL   = 3 * TILE;          // ends 65536
constexpr int SM_WMUL = 65536;
constexpr int SM_WSC  = 68608;
constexpr int SM_RBF6 = 71680;
constexpr int SM_BIAS = 74752;
constexpr int SM_END  = 75264;
constexpr int SMEM_DYN = SM_END + 1024 + 128;   // ~76.4 KB -> 2 CTAs/SM

// ---------------- launch 0: rbf + zero PA buffers ----------------
__global__ void rbf_kernel(const float* __restrict__ R,
                           const int* __restrict__ idx_i,
                           const int* __restrict__ idx_j,
                           float* __restrict__ rbf,
                           float* __restrict__ pa4)
{
    const float PI_F = 3.14159265358979323846f;
    const float c = sqrtf(2.f / 5.f);
    int gtid = blockIdx.x * blockDim.x + threadIdx.x;
    int gstr = gridDim.x * blockDim.x;
    size_t pn = (size_t)4*NA*128/4;
    float4 z = make_float4(0.f,0.f,0.f,0.f);
    for (size_t i = gtid; i < pn; i += gstr) ((float4*)pa4)[i] = z;
    for (int e = gtid; e < EG; e += gstr) {
        int i = idx_i[e], j = idx_j[e];
        float dx = R[3*i+0] - R[3*j+0];
        float dy = R[3*i+1] - R[3*j+1];
        float dz = R[3*i+2] - R[3*j+2];
        float d = sqrtf(dx*dx + dy*dy + dz*dz);
        d = fmaxf(d, 1e-2f);
        float inv = 1.f / d;
        float arg = d * (PI_F / 5.f);
        float s1, c1;
        __sincosf(arg, &s1, &c1);
        float tc = 2.f * c1;
        float sm1 = 0.f, s = s1;
        #pragma unroll
        for (int r = 0; r < NR; r++) {
            rbf[(size_t)e*NR + r] = c * s * inv;
            float nx = tc * s - sm1;
            sm1 = s; s = nx;
        }
    }
}

__global__ void x0_kernel(const int* __restrict__ Z,
                          const float* __restrict__ emb,
                          float* __restrict__ x0)
{
    size_t total = (size_t)NA * E;
    for (size_t idx = blockIdx.x * (size_t)blockDim.x + threadIdx.x; idx < total;
         idx += (size_t)gridDim.x * blockDim.x) {
        int a = (int)(idx >> 7);
        int c = (int)(idx & 127);
        x0[idx] = emb[(size_t)Z[a]*E + c];
    }
}

// coalesced buildcat
__global__ __launch_bounds__(128) void buildcat_kernel(
    const int* __restrict__ Z,
    const int* __restrict__ idx_i,
    const int* __restrict__ idx_j,
    const float* __restrict__ emb,
    const float* __restrict__ Wrbf,
    const float* __restrict__ rbf,
    __nv_bfloat16* __restrict__ ch_,
    __nv_bfloat16* __restrict__ cl_)
{
    __shared__ float ws[NR*E];
    for (int k = threadIdx.x; k < NR*E; k += 128) ws[k] = Wrbf[k];
    __syncthreads();
    int half = threadIdx.x >> 6;
    int c2 = threadIdx.x & 63;
    int c0 = c2 * 2;
    for (int eb = blockIdx.x * 2; eb < EG; eb += gridDim.x * 2) {
        int e = eb + half;
        if (e >= EG) continue;
        int ai = idx_i[e], aj = idx_j[e];
        float r0 = rbf[(size_t)e*NR+0], r1 = rbf[(size_t)e*NR+1], r2 = rbf[(size_t)e*NR+2];
        float r3 = rbf[(size_t)e*NR+3], r4 = rbf[(size_t)e*NR+4], r5 = rbf[(size_t)e*NR+5];
        float s0 = r0*ws[c0]     + r1*ws[E+c0]     + r2*ws[2*E+c0]
                 + r3*ws[3*E+c0] + r4*ws[4*E+c0]   + r5*ws[5*E+c0];
        float s1 = r0*ws[c0+1]   + r1*ws[E+c0+1]   + r2*ws[2*E+c0+1]
                 + r3*ws[3*E+c0+1] + r4*ws[4*E+c0+1] + r5*ws[5*E+c0+1];
        s0 = silu_f(s0); s1 = silu_f(s1);
        float2 vi = *(const float2*)&emb[(size_t)Z[ai]*E + c0];
        float2 vj = *(const float2*)&emb[(size_t)Z[aj]*E + c0];
        size_t base = (size_t)e * 384;
        float l0, l1;
        uint32_t h;
        h = pack_bf16_hi(vi.x, vi.y, l0, l1);
        *(uint32_t*)&ch_[base + c0] = h;
        *(uint32_t*)&cl_[base + c0] = pack_bf16(l0, l1);
        h = pack_bf16_hi(vj.x, vj.y, l0, l1);
        *(uint32_t*)&ch_[base + 128 + c0] = h;
        *(uint32_t*)&cl_[base + 128 + c0] = pack_bf16(l0, l1);
        h = pack_bf16_hi(s0, s1, l0, l1);
        *(uint32_t*)&ch_[base + 256 + c0] = h;
        *(uint32_t*)&cl_[base + 256 + c0] = pack_bf16(l0, l1);
    }
}

// ---- batched transpose+split ----
struct TsplitJobs {
    const float* src[8];
    float* dst_h[8];
    float* dst_l[8];
    int K[8];
    int tot[8];
};
__global__ void tsplit_all_kernel(TsplitJobs jobs)
{
    int j = blockIdx.y;
    const float* s = jobs.src[j];
    __nv_bfloat16* h = (__nv_bfloat16*)jobs.dst_h[j];
    __nv_bfloat16* l = (__nv_bfloat16*)jobs.dst_l[j];
    int K = jobs.K[j];
    int tot = jobs.tot[j];
    int per = K * 128;
    for (int idx = blockIdx.x * blockDim.x + threadIdx.x; idx < tot;
         idx += gridDim.x * blockDim.x) {
        int b = idx / per;
        int rem = idx - b * per;
        int k = rem >> 7, n = rem & 127;
        float v = s[idx];
        __nv_bfloat16 hi = __float2bfloat16(v);
        float lo = v - __bfloat162float(hi);
        h[(size_t)b*per + (size_t)n*K + k] = hi;
        l[(size_t)b*per + (size_t)n*K + k] = __float2bfloat16(lo);
    }
}

// ---------------- mma.sync bf16x3 GEMM, single-buffer, 2 CTAs/SM ----------------
__global__ __launch_bounds__(256, 2) void gemm_mma(
    const float* __restrict__ A,
    const __nv_bfloat16* __restrict__ A16h,
    const __nv_bfloat16* __restrict__ A16l,
    const __nv_bfloat16* __restrict__ Bh,
    const __nv_bfloat16* __restrict__ Bl,
    const float* __restrict__ bias,
    const float* __restrict__ mulW,
    const float* __restrict__ addp,
    const float* __restrict__ scW,
    const int* __restrict__ sc_idx, float* __restrict__ sc_out,
    const float* __restrict__ rbf,
    float* __restrict__ C,
    __nv_bfloat16* __restrict__ C16h,
    __nv_bfloat16* __restrict__ C16l,
    __half* __restrict__ Cf16,
    int M, int K, int act)
{
    extern __shared__ char smraw[];
    char* sm = (char*)(((uintptr_t)smraw + 1023) & ~(uintptr_t)1023);
    uint32_t smb = smem_u32(sm);
    float* wmul_s = (float*)(sm + SM_WMUL);
    float* wsc_s  = (float*)(sm + SM_WSC);
    float* rbf6   = (float*)(sm + SM_RBF6);
    float* bias_s = (float*)(sm + SM_BIAS);

    int tid = threadIdx.x;
    int lane = tid & 31;
    int wid = tid >> 5;
    int bm = blockIdx.x * 128;
    int need_rbf = (mulW != nullptr) || (scW != nullptr);

    for (int k = tid; k < NR*E; k += 256) {
        if (mulW) wmul_s[k] = mulW[k];
        if (scW)  wsc_s[k]  = scW[k];
    }
    for (int k = tid; k < E; k += 256) bias_s[k] = bias ? bias[k] : 0.f;
    if (need_rbf && tid < 128) {
        int g = bm + tid; if (g >= M) g = M - 1;
        #pragma unroll
        for (int q = 0; q < NR; q++) rbf6[tid*NR + q] = rbf[(size_t)g*NR + q];
    }
    __syncthreads();

    int wm = (wid & 3) * 32;
    int wn = (wid >> 2) * 64;
    int lq = lane >> 2;
    int lr4 = lane & 3;
    int r  = lane & 7;
    int mi = lane >> 3;
    uint32_t AHb = smb + SM_AH + (uint32_t)((wm + (mi&1)*8 + r) * 128);
    uint32_t ALb = AHb + TILE;
    int a_chsel = mi >> 1;
    uint32_t BHb = smb + SM_BH + (uint32_t)((wn + ((mi>>1)&1)*8 + r) * 128);
    uint32_t BLb = BHb + TILE;
    int b_chsel = mi & 1;

    float acc[2][8][4];
    #pragma unroll
    for (int a0 = 0; a0 < 2; a0++)
        #pragma unroll
        for (int b0 = 0; b0 < 8; b0++)
            #pragma unroll
            for (int c0 = 0; c0 < 4; c0++) acc[a0][b0][c0] = 0.f;

    int nch = K >> 6;
    for (int c = 0; c < nch; c++) {
        int kc = c << 6;

        #pragma unroll
        for (int u = 0; u < 8; u++) {
            int f = u*256 + tid;
            int which = f >> 10;
            int g2 = f & 1023;
            int n = g2 >> 3, ch = g2 & 7;
            const __nv_bfloat16* src = (which ? Bl : Bh) + (size_t)n*K + kc + ch*8;
            uint32_t dst = smb + (which ? SM_BL : SM_BH)
                         + (uint32_t)(n*128 + ((ch ^ (n & 7)) << 4));
            CP_ASYNC16(dst, src);
        }
        if (A16h) {
            #pragma unroll
            for (int u = 0; u < 8; u++) {
                int f = u*256 + tid;
                int which = f >> 10;
                int g2 = f & 1023;
                int rr = g2 >> 3, ch = g2 & 7;
                int g = bm + rr; if (g >= M) g = M - 1;
                const __nv_bfloat16* src = (which ? A16l : A16h) + (size_t)g*K + kc + ch*8;
                uint32_t dst = smb + (which ? SM_AL : SM_AH)
                             + (uint32_t)(rr*128 + ((ch ^ (rr & 7)) << 4));
                CP_ASYNC16(dst, src);
            }
            CP_COMMIT();
            CP_WAIT0();
        } else {
            CP_COMMIT();
            #pragma unroll
            for (int u = 0; u < 4; u++) {
                int f = u*256 + tid;
                int rr = f >> 3, ch = f & 7;
                int g = bm + rr;
                int k = kc + ch*8;
                float v[8];
                if (g < M) {
                    float4 p0 = *(const float4*)&A[(size_t)g*K + k];
                    float4 p1 = *(const float4*)&A[(size_t)g*K + k + 4];
                    v[0]=p0.x; v[1]=p0.y; v[2]=p0.z; v[3]=p0.w;
                    v[4]=p1.x; v[5]=p1.y; v[6]=p1.z; v[7]=p1.w;
                } else {
                    #pragma unroll
                    for (int e2 = 0; e2 < 8; e2++) v[e2] = 0.f;
                }
                uint4 hb, lb;
                float l0, l1;
                hb.x = pack_bf16_hi(v[0], v[1], l0, l1); lb.x = pack_bf16(l0, l1);
                hb.y = pack_bf16_hi(v[2], v[3], l0, l1); lb.y = pack_bf16(l0, l1);
                hb.z = pack_bf16_hi(v[4], v[5], l0, l1); lb.z = pack_bf16(l0, l1);
                hb.w = pack_bf16_hi(v[6], v[7], l0, l1); lb.w = pack_bf16(l0, l1);
                uint32_t sw = (uint32_t)(rr*128 + ((ch ^ (rr & 7)) << 4));
                *(uint4*)(sm + SM_AH + sw) = hb;
                *(uint4*)(sm + SM_AL + sw) = lb;
            }
            CP_WAIT0();
        }
        __syncthreads();

        #pragma unroll
        for (int ks = 0; ks < 4; ks++) {
            uint32_t aswz = (uint32_t)(((2*ks + a_chsel) ^ r) << 4);
            uint32_t bswz = (uint32_t)(((2*ks + b_chsel) ^ r) << 4);
            uint32_t ah[2][4], al[2][4];
            LDSM4(ah[0], AHb + aswz);
            LDSM4(ah[1], AHb + 2048 + aswz);
            LDSM4(al[0], ALb + aswz);
            LDSM4(al[1], ALb + 2048 + aswz);
            #pragma unroll
            for (int p = 0; p < 4; p++) {
                uint32_t bh[4], bl[4];
                LDSM4(bh, BHb + (uint32_t)(p*2048) + bswz);
                LDSM4(bl, BLb + (uint32_t)(p*2048) + bswz);
                #pragma unroll
                for (int mt = 0; mt < 2; mt++) {
                    MMA_BF16(acc[mt][2*p+0], ah[mt], bh[0], bh[1]);
                    MMA_BF16(acc[mt][2*p+0], ah[mt], bl[0], bl[1]);
                    MMA_BF16(acc[mt][2*p+0], al[mt], bh[0], bh[1]);
                    MMA_BF16(acc[mt][2*p+1], ah[mt], bh[2], bh[3]);
                    MMA_BF16(acc[mt][2*p+1], ah[mt], bl[2], bl[3]);
                    MMA_BF16(acc[mt][2*p+1], al[mt], bh[2], bh[3]);
                }
            }
        }
        __syncthreads();
    }

    // ---- epilogue (R15-exact + optional fp16 output) ----
    #pragma unroll
    for (int mt = 0; mt < 2; mt++) {
        int lrbase = wm + mt*16 + lq;
        #pragma unroll
        for (int h = 0; h < 2; h++) {
            int lrow = lrbase + h*8;
            int row = bm + lrow;
            if (row >= M) continue;
            int asc = scW ? sc_idx[row] : 0;
            #pragma unroll
            for (int nt = 0; nt < 8; nt++) {
                int col = wn + nt*8 + lr4*2;
                float v0 = acc[mt][nt][2*h+0] + bias_s[col];
                float v1 = acc[mt][nt][2*h+1] + bias_s[col+1];
                if (act) { v0 = silu_f(v0); v1 = silu_f(v1); }
                if (mulW) {
                    float d0 = 0.f, d1 = 0.f;
                    #pragma unroll
                    for (int q = 0; q < NR; q++) {
                        float rq = rbf6[lrow*NR + q];
                        d0 += rq * wmul_s[q*E + col];
                        d1 += rq * wmul_s[q*E + col + 1];
                    }
                    v0 *= d0; v1 *= d1;
                }
                if (addp) {
                    float2 av = *(const float2*)&addp[(size_t)row*128 + col];
                    v0 += av.x; v1 += av.y;
                }
                if (C) *(float2*)&C[(size_t)row*128 + col] = make_float2(v0, v1);
                if (C16h) {
                    float l0, l1;
                    uint32_t hb = pack_bf16_hi(v0, v1, l0, l1);
                    uint32_t lb = pack_bf16(l0, l1);
                    *(uint32_t*)&C16h[(size_t)row*128 + col] = hb;
                    *(uint32_t*)&C16l[(size_t)row*128 + col] = lb;
                }
                if (Cf16) {
                    __half2 hv = __floats2half2_rn(v0, v1);
                    *(__half2*)&Cf16[(size_t)row*128 + col] = hv;
                }
                if (scW) {
                    float g0 = 0.f, g1 = 0.f;
                    #pragma unroll
                    for (int q = 0; q < NR; q++) {
                        float rq = rbf6[lrow*NR + q];
                        g0 += rq * wsc_s[q*E + col];
                        g1 += rq * wsc_s[q*E + col + 1];
                    }
                    RED2(&sc_out[(size_t)asc*128 + col], g0*v0, g1*v1);
                }
            }
        }
    }
}

// ---------------- triplet messages + atomic scatter (fp16 xkj gather, unroll x2) ----------------
__global__ __launch_bounds__(256) void triplet_kernel(
    const __half* __restrict__ xkj,
    const float* __restrict__ cosik,
    const int* __restrict__ idx_kj,
    const int* __restrict__ idx_ji,
    const float* __restrict__ Wabf,       // [7,128]
    float* __restrict__ aggr)
{
    __shared__ float ws[NABF*E];
    for (int k = threadIdx.x; k < NABF*E; k += 256) ws[k] = Wabf[k];
    __syncthreads();
    int lane = threadIdx.x & 31;
    int warp = (blockIdx.x * 256 + threadIdx.x) >> 5;
    int nwarps = (gridDim.x * 256) >> 5;
    int c = lane << 2;
    for (int t = warp * 2; t < TT; t += nwarps * 2) {
        int ekj0 = idx_kj[t],   eji0 = idx_ji[t];
        int ekj1 = idx_kj[t+1], eji1 = idx_ji[t+1];
        float xa = fminf(1.f, fmaxf(-1.f, cosik[t]));
        float xb = fminf(1.f, fmaxf(-1.f, cosik[t+1]));
        uint2 raw0 = *(const uint2*)&xkj[(size_t)ekj0*128 + c];
        uint2 raw1 = *(const uint2*)&xkj[(size_t)ekj1*128 + c];
        float2 p00 = __half22float2(*(__half2*)&raw0.x);
        float2 p01 = __half22float2(*(__half2*)&raw0.y);
        float2 p10 = __half22float2(*(__half2*)&raw1.x);
        float2 p11 = __half22float2(*(__half2*)&raw1.y);
        float xv0[4] = {p00.x, p00.y, p01.x, p01.y};
        float xv1[4] = {p10.x, p10.y, p11.x, p11.y};
        float a1=xa, a2=2.f*xa*a1-1.f, a3=2.f*xa*a2-a1, a4=2.f*xa*a3-a2,
              a5=2.f*xa*a4-a3, a6=2.f*xa*a5-a4;
        float b1=xb, b2=2.f*xb*b1-1.f, b3=2.f*xb*b2-b1, b4=2.f*xb*b3-b2,
              b5=2.f*xb*b4-b3, b6=2.f*xb*b5-b4;
        float m0[4], m1[4];
        #pragma unroll
        for (int j = 0; j < 4; j++) {
            int cc = c + j;
            float w0=ws[cc], w1=ws[E+cc], w2=ws[2*E+cc], w3=ws[3*E+cc],
                  w4=ws[4*E+cc], w5=ws[5*E+cc], w6=ws[6*E+cc];
            m0[j] = w0 + a1*w1 + a2*w2 + a3*w3 + a4*w4 + a5*w5 + a6*w6;
            m1[j] = w0 + b1*w1 + b2*w2 + b3*w3 + b4*w4 + b5*w5 + b6*w6;
        }
        RED4(&aggr[(size_t)eji0*128 + c], xv0[0]*m0[0], xv0[1]*m0[1], xv0[2]*m0[2], xv0[3]*m0[3]);
        RED4(&aggr[(size_t)eji1*128 + c], xv1[0]*m1[0], xv1[1]*m1[1], xv1[2]*m1[2], xv1[3]*m1[3]);
    }
}

// ---------------- final molecule reduction ----------------
__global__ void final_kernel(const float* __restrict__ ro,
                             const float* __restrict__ rs,
                             const int* __restrict__ bseg,
                             const float* __restrict__ cmp_p,
                             const float* __restrict__ csg_p,
                             float* __restrict__ out)
{
    float cmp = cmp_p[0], csg = csg_p[0];
    size_t total = (size_t)NA * 32;
    for (size_t idx = blockIdx.x * (size_t)blockDim.x + threadIdx.x; idx < total;
         idx += (size_t)gridDim.x * blockDim.x) {
        int a = (int)(idx >> 5);
        int c = (int)(idx & 31) << 2;
        int m = bseg[a];
        float4 o = *(const float4*)&ro[(size_t)a*128 + c];
        float4 s = *(const float4*)&rs[(size_t)a*128 + c];
        RED4(&out[(size_t)m*128 + c],
             cmp*o.x + csg*s.x, cmp*o.y + csg*s.y,
             cmp*o.z + csg*s.z, cmp*o.w + csg*s.w);
    }
}

// ---------------- host orchestration (serial stream 0) ----------------
extern "C" void kernel_launch(void* const* d_in, const int* in_sizes, int n_in,
                              void* d_out, int out_size)
{
    const int*   Z      = (const int*)  d_in[0];
    const float* R      = (const float*)d_in[1];
    const int*   bseg   = (const int*)  d_in[2];
    const int*   idx_i  = (const int*)  d_in[3];
    const int*   idx_j  = (const int*)  d_in[4];
    const int*   idx_kj = (const int*)  d_in[5];
    const int*   idx_ji = (const int*)  d_in[6];
    const float* cosik  = (const float*)d_in[7];
    const float* emb    = (const float*)d_in[8];
    const float* Wrbf   = (const float*)d_in[9];
    const float* Wemb   = (const float*)d_in[10];
    const float* bemb   = (const float*)d_in[11];
    const float* Worbf  = (const float*)d_in[12];
    const float* Wo1    = (const float*)d_in[13];
    const float* bo1    = (const float*)d_in[14];
    const float* Wout   = (const float*)d_in[15];
    const float* Wid1   = (const float*)d_in[16];
    const float* bid1   = (const float*)d_in[17];
    const float* Wid2   = (const float*)d_in[18];
    const float* Wji    = (const float*)d_in[19];
    const float* bji    = (const float*)d_in[20];
    const float* Wkj    = (const float*)d_in[21];
    const float* bkj    = (const float*)d_in[22];
    const float* Wirbf  = (const float*)d_in[23];
    const float* Wabf   = (const float*)d_in[24];
    const float* Wres   = (const float*)d_in[25];
    const float* bres   = (const float*)d_in[26];
    const float* cmp    = (const float*)d_in[27];
    const float* csg    = (const float*)d_in[28];
    float* out = (float*)d_out;

    cudaFuncSetAttribute(gemm_mma, cudaFuncAttributeMaxDynamicSharedMemorySize, SMEM_DYN);

    float* buf = nullptr;
    cudaGetSymbolAddress((void**)&buf, g_buf);
    float* RBF   = buf + OFF_RBF;
    __nv_bfloat16* CATH = (__nv_bfloat16*)(buf + OFF_CATH);
    __nv_bfloat16* CATL = (__nv_bfloat16*)(buf + OFF_CATL);
    __nv_bfloat16* XH   = (__nv_bfloat16*)(buf + OFF_XH);
    __nv_bfloat16* XL   = (__nv_bfloat16*)(buf + OFF_XL);
    __half* XKJ16 = (__half*)(buf + OFF_XKJ);
    float* AGGR  = buf + OFF_AGGR;
    float* PA    = buf + OFF_PA;
    float* HAT   = buf + OFF_HAT;
    float* ROUT  = buf + OFF_ROUT;
    float* RSING = buf + OFF_RSING;
    float* STMP  = buf + OFF_STMP;
    float* X0    = buf + OFF_X0;
    float* WT    = buf + OFF_WT;

    #define BF(off) ((__nv_bfloat16*)(WT + (off)))
    #define PAB(b)  (PA + (size_t)(b)*NA*128)

    const int GE = (EG + 127) / 128;
    const int GA = (NA + 127) / 128;

    // launch 0: rbf + zero 4 PA buffers
    rbf_kernel<<<1024, 256>>>(R, idx_i, idx_j, RBF, PA);
    // launch 1: buildcat
    buildcat_kernel<<<4096, 128>>>(Z, idx_i, idx_j, emb, Wrbf, RBF, CATH, CATL);
    // launch 2: all weight splits
    {
        TsplitJobs j;
        j.src[0]=Wemb; j.dst_h[0]=(float*)BF(WT_EMB_H); j.dst_l[0]=(float*)BF(WT_EMB_L); j.K[0]=384; j.tot[0]=384*128;
        j.src[1]=Wo1;  j.dst_h[1]=(float*)BF(WT_O1_H);  j.dst_l[1]=(float*)BF(WT_O1_L);  j.K[1]=128; j.tot[1]=4*128*128;
        j.src[2]=Wout; j.dst_h[2]=(float*)BF(WT_OUT_H); j.dst_l[2]=(float*)BF(WT_OUT_L); j.K[2]=128; j.tot[2]=4*128*128;
        j.src[3]=Wid1; j.dst_h[3]=(float*)BF(WT_ID1_H); j.dst_l[3]=(float*)BF(WT_ID1_L); j.K[3]=128; j.tot[3]=4*128*128;
        j.src[4]=Wid2; j.dst_h[4]=(float*)BF(WT_ID2_H); j.dst_l[4]=(float*)BF(WT_ID2_L); j.K[4]=128; j.tot[4]=4*128*128;
        j.src[5]=Wji;  j.dst_h[5]=(float*)BF(WT_JI_H);  j.dst_l[5]=(float*)BF(WT_JI_L);  j.K[5]=128; j.tot[5]=3*128*128;
        j.src[6]=Wkj;  j.dst_h[6]=(float*)BF(WT_KJ_H);  j.dst_l[6]=(float*)BF(WT_KJ_L);  j.K[6]=128; j.tot[6]=3*128*128;
        j.src[7]=Wres; j.dst_h[7]=(float*)BF(WT_RES_H); j.dst_l[7]=(float*)BF(WT_RES_L); j.K[7]=128; j.tot[7]=3*128*128;
        tsplit_all_kernel<<<dim3(64, 8), 256>>>(j);
    }

    // launch 3: embedding GEMM  <-- ncu capture target
    gemm_mma<<<GE, 256, SMEM_DYN>>>(nullptr, CATH, CATL,
                                    BF(WT_EMB_H), BF(WT_EMB_L), bemb,
                                    nullptr, nullptr,
                                    Worbf, idx_i, PAB(0), RBF,
                                    nullptr, XH, XL, nullptr, EG, 384, 1);
    // launch 4: x0 gather
    x0_kernel<<<1024, 256>>>(Z, emb, X0);

    for (int i = 0; i < NB; i++) {
        size_t wo = (size_t)i * 128 * 128;
        // x_kj (fp16 out) = silu(x@Wkj+b) * (rbf@Wirbf)
        gemm_mma<<<GE, 256, SMEM_DYN>>>(nullptr, XH, XL,
                                        BF(WT_KJ_H) + wo, BF(WT_KJ_L) + wo, bkj + (size_t)i*E,
                                        Wirbf + (size_t)i*NR*E, nullptr,
                                        nullptr, nullptr, nullptr, RBF,
                                        nullptr, nullptr, nullptr, XKJ16, EG, 128, 1);
        gemm_mma<<<GE, 256, SMEM_DYN>>>(nullptr, XH, XL,
                                        BF(WT_JI_H) + wo, BF(WT_JI_L) + wo, bji + (size_t)i*E,
                                        nullptr, nullptr, nullptr, nullptr, nullptr, nullptr,
                                        AGGR, nullptr, nullptr, nullptr, EG, 128, 1);
        triplet_kernel<<<2048, 256>>>(XKJ16, cosik, idx_kj, idx_ji,
                                      Wabf + (size_t)i*NABF*E, AGGR);
        gemm_mma<<<GE, 256, SMEM_DYN>>>(AGGR, nullptr, nullptr,
                                        BF(WT_RES_H) + wo, BF(WT_RES_L) + wo, bres + (size_t)i*E,
                                        nullptr, AGGR,
                                        Worbf + (size_t)(i+1)*NR*E, idx_i, PAB(i+1), RBF,
                                        nullptr, XH, XL, nullptr, EG, 128, 1);
    }

    // output chains (blocks 0..3)
    for (int b = 0; b <= NB; b++) {
        size_t wo1 = (size_t)b * 128 * 128;
        gemm_mma<<<GA, 256, SMEM_DYN>>>(PAB(b), nullptr, nullptr,
                                        BF(WT_O1_H) + wo1, BF(WT_O1_L) + wo1, bo1 + (size_t)b*E,
                                        nullptr, nullptr, nullptr, nullptr, nullptr, nullptr,
                                        HAT, nullptr, nullptr, nullptr, NA, 128, 1);
        gemm_mma<<<GA, 256, SMEM_DYN>>>(HAT, nullptr, nullptr,
                                        BF(WT_OUT_H) + wo1, BF(WT_OUT_L) + wo1, nullptr,
                                        nullptr, (b == 0) ? nullptr : ROUT,
                                        nullptr, nullptr, nullptr, nullptr,
                                        ROUT, nullptr, nullptr, nullptr, NA, 128, 0);
    }

    // identity chain
    gemm_mma<<<GA, 256, SMEM_DYN>>>(X0, nullptr, nullptr, BF(WT_ID1_H), BF(WT_ID1_L), bid1,
                                    nullptr, nullptr, nullptr, nullptr, nullptr, nullptr,
                                    STMP, nullptr, nullptr, nullptr, NA, 128, 1);
    gemm_mma<<<GA, 256, SMEM_DYN>>>(STMP, nullptr, nullptr, BF(WT_ID2_H), BF(WT_ID2_L), nullptr,
                                    nullptr, nullptr, nullptr, nullptr, nullptr, nullptr,
                                    RSING, nullptr, nullptr, nullptr, NA, 128, 0);
    for (int b = 1; b <= NB; b++) {
        size_t wo1 = (size_t)b * 128 * 128;
        gemm_mma<<<GA, 256, SMEM_DYN>>>(RSING, nullptr, nullptr,
                                        BF(WT_ID1_H) + wo1, BF(WT_ID1_L) + wo1, bid1 + (size_t)b*E,
                                        nullptr, nullptr, nullptr, nullptr, nullptr, nullptr,
                                        STMP, nullptr, nullptr, nullptr, NA, 128, 1);
        gemm_mma<<<GA, 256, SMEM_DYN>>>(STMP, nullptr, nullptr,
                                        BF(WT_ID2_H) + wo1, BF(WT_ID2_L) + wo1, nullptr,
                                        nullptr, RSING, nullptr, nullptr, nullptr, nullptr,
                                        RSING, nullptr, nullptr, nullptr, NA, 128, 0);
    }

    // final
    cudaMemsetAsync(out, 0, (size_t)NM*E*sizeof(float));
    final_kernel<<<512, 256>>>(ROUT, RSING, bseg, cmp, csg, out);
}